// round 13
// baseline (speedup 1.0000x reference)
#include <cuda_runtime.h>
#include <cuda_bf16.h>
#include <cstdint>
#include <math.h>

typedef __nv_bfloat16 bf16;

// Problem constants
#define Bb 8
#define Ss_ 512
#define Mm 8
#define Dd 512
#define Hh 8
#define DH 64
#define SSq 16
#define KSn 16
#define SMf 4096
#define NKEY (SMf + KSn)
#define SCALE 0.125f
#define CH 257

#define TROWS (Bb*Ss_*Mm)  // 32768
#define SROWS (Bb*SSq)     // 128

// ---------------------------------------------------------------------------
// Scratch (device globals — no allocation allowed)
// ---------------------------------------------------------------------------
__device__ float g_qt[(size_t)TROWS*Dd];
__device__ float g_kt[(size_t)TROWS*Dd];
__device__ float g_vt[(size_t)TROWS*Dd];
__device__ float g_qkvt[(size_t)TROWS*Dd];
__device__ float g_qs[(size_t)SROWS*Dd];
__device__ float g_ks[(size_t)SROWS*Dd];
__device__ float g_vs[(size_t)SROWS*Dd];
__device__ float g_qkvs[(size_t)SROWS*Dd];
__device__ bf16 g_wth[4][(size_t)Dd*Dd];
__device__ bf16 g_wtl[4][(size_t)Dd*Dd];
__device__ float g_smax[64*16*16];
__device__ float g_ssum[64*16*16];
__device__ float g_pout[(size_t)64*16*4*16*64];

// ---------------------------------------------------------------------------
__device__ __forceinline__ uint32_t bf2u(__nv_bfloat162 v) {
    return *reinterpret_cast<uint32_t*>(&v);
}
__device__ __forceinline__ void split2(float x, float y, uint32_t& h, uint32_t& l) {
    __nv_bfloat162 H = __floats2bfloat162_rn(x, y);
    float hx = __bfloat162float(H.x), hy = __bfloat162float(H.y);
    __nv_bfloat162 L = __floats2bfloat162_rn(x - hx, y - hy);
    h = bf2u(H); l = bf2u(L);
}

__device__ __forceinline__ void mma16816(float* c,
    uint32_t a0, uint32_t a1, uint32_t a2, uint32_t a3,
    uint32_t b0, uint32_t b1)
{
    asm volatile(
        "mma.sync.aligned.m16n8k16.row.col.f32.bf16.bf16.f32 "
        "{%0,%1,%2,%3}, {%4,%5,%6,%7}, {%8,%9}, {%0,%1,%2,%3};"
        : "+f"(c[0]), "+f"(c[1]), "+f"(c[2]), "+f"(c[3])
        : "r"(a0), "r"(a1), "r"(a2), "r"(a3), "r"(b0), "r"(b1));
}

__device__ __forceinline__ void ldsm4(uint32_t* r, uint32_t addr) {
    asm volatile(
        "ldmatrix.sync.aligned.m8n8.x4.shared.b16 {%0,%1,%2,%3}, [%4];"
        : "=r"(r[0]), "=r"(r[1]), "=r"(r[2]), "=r"(r[3]) : "r"(addr));
}

__device__ __forceinline__ void cp16(uint32_t smem_dst, const void* gsrc) {
    asm volatile("cp.async.cg.shared.global [%0], [%1], 16;"
                 :: "r"(smem_dst), "l"(gsrc));
}
__device__ __forceinline__ void cp_commit() {
    asm volatile("cp.async.commit_group;" ::: "memory");
}
template<int N>
__device__ __forceinline__ void cp_wait() {
    asm volatile("cp.async.wait_group %0;" :: "n"(N) : "memory");
}

// ---------------------------------------------------------------------------
// Weight transpose + split
// ---------------------------------------------------------------------------
struct WArgs { const float* W[4]; bf16* Wh[4]; bf16* Wl[4]; };

__global__ __launch_bounds__(256) void wsplit_kernel(WArgs a) {
    const int z = blockIdx.z;
    const float* W = a.W[z];
    bf16* Wh = a.Wh[z];
    bf16* Wl = a.Wl[z];
    __shared__ float t[32][33];
    const int x0 = blockIdx.x * 32, y0 = blockIdx.y * 32;
    const int tx = threadIdx.x, ty = threadIdx.y;
#pragma unroll
    for (int i = ty; i < 32; i += 8)
        t[i][tx] = W[(size_t)(y0 + i) * Dd + x0 + tx];
    __syncthreads();
#pragma unroll
    for (int i = ty; i < 32; i += 8) {
        float v = t[tx][i];
        bf16 h = __float2bfloat16(v);
        bf16 l = __float2bfloat16(v - __bfloat162float(h));
        size_t o = (size_t)(x0 + i) * Dd + y0 + tx;
        Wh[o] = h; Wl[o] = l;
    }
}

// ---------------------------------------------------------------------------
// MMA GEMM (round-10 version — best measured)
// ---------------------------------------------------------------------------
struct GB { const float* A; const bf16* Wh; const bf16* Wl;
            const float* bias; float* C; int rows; };
struct GBatch { GB g[6]; };

#define BK 32
#define KPAD 40
#define ARR_B   (128*KPAD*2)
#define STAGE_B (4*ARR_B)
#define DSMEM_B (2*STAGE_B)

__global__ __launch_bounds__(256, 2) void mma_gemm(GBatch batch) {
    const GB a = batch.g[blockIdx.z];
    const int brow = blockIdx.y * 128;
    if (brow >= a.rows) return;
    const int bcol = blockIdx.x * 128;

    extern __shared__ __align__(16) char dsm[];
    bf16* const sb = (bf16*)dsm;
    uint32_t smem_u32;
    {
        uint64_t t = __cvta_generic_to_shared(dsm);
        smem_u32 = (uint32_t)t;
    }

    const int tid = threadIdx.x;
    const int wid = tid >> 5, lane = tid & 31;
    const int warpM = wid & 3;
    const int warpN = wid >> 2;
    const int ra = lane >> 2;
    const int tk = (lane & 3) * 2;

    const int g8 = lane >> 3;
    const int r8 = lane & 7;
    const uint32_t a_ld_off = (uint32_t)((warpM*32 + (g8 & 1)*8 + r8) * KPAD
                                         + (g8 >> 1)*8) * 2;
    const uint32_t w_ld_off = (uint32_t)((warpN*64 + (g8 >> 1)*8 + r8) * KPAD
                                         + (g8 & 1)*8) * 2;

    const int ar = tid >> 1;
    const int ac = (tid & 1) * 4;
    const float* gA = a.A + (size_t)(brow + ar) * Dd + ac * 4;
    const int warr = tid >> 7;
    const int wr = tid & 127;
    const bf16* gW = (warr ? a.Wl : a.Wh) + (size_t)(bcol + wr) * Dd;
    const uint32_t wdst0 = smem_u32 + (2 + warr) * ARR_B + wr * (KPAD*2);

    float acc[2][8][4];
#pragma unroll
    for (int mi = 0; mi < 2; mi++)
#pragma unroll
        for (int ni = 0; ni < 8; ni++)
#pragma unroll
            for (int j = 0; j < 4; j++) acc[mi][ni][j] = 0.f;

    float4 pA[4];
#pragma unroll
    for (int i = 0; i < 4; i++) pA[i] = *(const float4*)(gA + i * 4);
#pragma unroll
    for (int q = 0; q < 4; q++)
        cp16(wdst0 + q * 16, gW + q * 8);
    cp_commit();

    for (int it = 0; it < 16; it++) {
        const int cur = it & 1;
        bf16* const Ah = sb + cur * (STAGE_B/2);
        bf16* const Al = Ah + ARR_B/2;
        const uint32_t stage = smem_u32 + cur * STAGE_B;

#pragma unroll
        for (int i = 0; i < 4; i++) {
            float4 v = pA[i];
            uint32_t h0, l0, h1, l1;
            split2(v.x, v.y, h0, l0);
            split2(v.z, v.w, h1, l1);
            *(uint2*)(Ah + ar*KPAD + (ac + i)*4) = make_uint2(h0, h1);
            *(uint2*)(Al + ar*KPAD + (ac + i)*4) = make_uint2(l0, l1);
        }

        if (it + 1 < 16) {
            const int k1 = (it + 1) * BK;
#pragma unroll
            for (int i = 0; i < 4; i++)
                pA[i] = *(const float4*)(gA + k1 + i * 4);
            const uint32_t wd = wdst0 + (cur ^ 1) * STAGE_B;
#pragma unroll
            for (int q = 0; q < 4; q++)
                cp16(wd + q * 16, gW + k1 + q * 8);
            cp_commit();
            cp_wait<1>();
        } else {
            cp_wait<0>();
        }
        __syncthreads();

#pragma unroll
        for (int ks = 0; ks < 2; ks++) {
            const uint32_t kso = ks * 32;
            uint32_t ah[2][4], al[2][4];
#pragma unroll
            for (int mi = 0; mi < 2; mi++) {
                const uint32_t ao = a_ld_off + mi * (16*KPAD*2) + kso;
                ldsm4(ah[mi], stage + ao);
                ldsm4(al[mi], stage + ARR_B + ao);
            }
#pragma unroll
            for (int np = 0; np < 4; np++) {
                uint32_t wh[4], wl[4];
                const uint32_t wo = w_ld_off + np * (16*KPAD*2) + kso;
                ldsm4(wh, stage + 2*ARR_B + wo);
                ldsm4(wl, stage + 3*ARR_B + wo);
#pragma unroll
                for (int mi = 0; mi < 2; mi++) {
                    float* c0 = acc[mi][2*np];
                    float* c1 = acc[mi][2*np + 1];
                    mma16816(c0, ah[mi][0], ah[mi][1], ah[mi][2], ah[mi][3], wh[0], wh[1]);
                    mma16816(c0, ah[mi][0], ah[mi][1], ah[mi][2], ah[mi][3], wl[0], wl[1]);
                    mma16816(c0, al[mi][0], al[mi][1], al[mi][2], al[mi][3], wh[0], wh[1]);
                    mma16816(c1, ah[mi][0], ah[mi][1], ah[mi][2], ah[mi][3], wh[2], wh[3]);
                    mma16816(c1, ah[mi][0], ah[mi][1], ah[mi][2], ah[mi][3], wl[2], wl[3]);
                    mma16816(c1, al[mi][0], al[mi][1], al[mi][2], al[mi][3], wh[2], wh[3]);
                }
            }
        }
        __syncthreads();
    }

#pragma unroll
    for (int mi = 0; mi < 2; mi++) {
        int row0 = brow + warpM * 32 + mi * 16 + ra;
#pragma unroll
        for (int ni = 0; ni < 8; ni++) {
            int col = bcol + warpN * 64 + ni * 8 + tk;
            float bx = a.bias[col], by = a.bias[col + 1];
            float2 o0 = make_float2(acc[mi][ni][0] + bx, acc[mi][ni][1] + by);
            float2 o1 = make_float2(acc[mi][ni][2] + bx, acc[mi][ni][3] + by);
            *(float2*)(a.C + (size_t)row0 * Dd + col) = o0;
            *(float2*)(a.C + (size_t)(row0 + 8) * Dd + col) = o1;
        }
    }
}

// ---------------------------------------------------------------------------
// Temporal attention v4 (round-12 — measured good)
// ---------------------------------------------------------------------------
#define QP 68

__global__ __launch_bounds__(64) void temporal_attn_kernel(
    const float* __restrict__ Qt, const float* __restrict__ Kt,
    const float* __restrict__ Vt, const float* __restrict__ Ksp,
    const float* __restrict__ Vsp, const int* __restrict__ mt,
    const int* __restrict__ ms, float* __restrict__ w_t,
    float* __restrict__ qkvt)
{
    const int idx = blockIdx.x;
    const int s = idx % Ss_;
    const int h = (idx / Ss_) % Hh;
    const int b = idx / (Ss_ * Hh);
    const int d = threadIdx.x;

    __shared__ __align__(16) float q[Mm][QP], k[Mm][QP];
    __shared__ __align__(16) float ks[KSn][QP];
    __shared__ float sc[Mm][Mm+KSn];

    const size_t base_t = ((size_t)(b*Ss_ + s) * Mm) * Dd + (size_t)h * DH;
#pragma unroll
    for (int m = 0; m < Mm; m++) {
        q[m][d] = Qt[base_t + (size_t)m*Dd + d];
        k[m][d] = Kt[base_t + (size_t)m*Dd + d];
    }
    const size_t base_s = (size_t)b*KSn*Dd + (size_t)h*DH;
#pragma unroll
    for (int n = 0; n < KSn; n++)
        ks[n][d] = Ksp[base_s + (size_t)n*Dd + d];
    __syncthreads();

    for (int e = d; e < Mm*(Mm+KSn); e += 64) {
        int m = e / (Mm+KSn), n = e % (Mm+KSn);
        const float4* kp = (const float4*)((n < Mm) ? k[n] : ks[n-Mm]);
        const float4* qp = (const float4*)q[m];
        float acc = 0.f;
#pragma unroll
        for (int c = 0; c < DH/4; c++) {
            float4 av = qp[c], bv = kp[c];
            acc += av.x*bv.x + av.y*bv.y + av.z*bv.z + av.w*bv.w;
        }
        int maskv = (n < Mm) ? mt[(b*Ss_+s)*Mm + n] : ms[b*KSn + (n-Mm)];
        sc[m][n] = acc * SCALE + (maskv ? 0.f : -1e30f);
    }
    __syncthreads();

    {
        const int m = d >> 3;
        const int l = d & 7;
        float s0 = sc[m][l], s1 = sc[m][l+8], s2 = sc[m][l+16];
        float lm = fmaxf(s0, fmaxf(s1, s2));
#pragma unroll
        for (int o = 4; o > 0; o >>= 1)
            lm = fmaxf(lm, __shfl_xor_sync(0xffffffffu, lm, o, 8));
        float e0 = __expf(s0 - lm), e1 = __expf(s1 - lm), e2 = __expf(s2 - lm);
        float ls = e0 + e1 + e2;
#pragma unroll
        for (int o = 4; o > 0; o >>= 1)
            ls += __shfl_xor_sync(0xffffffffu, ls, o, 8);
        const float inv = 1.f / ls;
        e0 *= inv; e1 *= inv; e2 *= inv;
        sc[m][l] = e0; sc[m][l+8] = e1; sc[m][l+16] = e2;
        const size_t wbase = ((((size_t)(b*Hh+h)*Ss_ + s) * Mm) + m) * (Mm+KSn);
        w_t[wbase + l]      = e0;
        w_t[wbase + l + 8]  = e1;
        w_t[wbase + l + 16] = e2;
    }
    __syncthreads();

    {
        float accv[Mm];
#pragma unroll
        for (int m = 0; m < Mm; m++) accv[m] = 0.f;
#pragma unroll
        for (int n = 0; n < Mm; n++) {
            float vv = Vt[base_t + (size_t)n*Dd + d];
#pragma unroll
            for (int m = 0; m < Mm; m++) accv[m] += sc[m][n] * vv;
        }
#pragma unroll
        for (int n = 0; n < KSn; n++) {
            float vv = Vsp[base_s + (size_t)n*Dd + d];
#pragma unroll
            for (int m = 0; m < Mm; m++) accv[m] += sc[m][Mm+n] * vv;
        }
#pragma unroll
        for (int m = 0; m < Mm; m++)
            qkvt[base_t + (size_t)m*Dd + d] = accv[m];
    }
}

// ---------------------------------------------------------------------------
// Static attention pass 1 (unchanged)
// ---------------------------------------------------------------------------
__global__ __launch_bounds__(256) void static_pass1(
    const float* __restrict__ Qs, const float* __restrict__ Ktf,
    const float* __restrict__ Vtf, const float* __restrict__ Ksp,
    const float* __restrict__ Vsp, const int* __restrict__ mt,
    const int* __restrict__ ms, float* __restrict__ w_s,
    float* __restrict__ smax, float* __restrict__ ssum,
    float* __restrict__ pout)
{
    const int chunk = blockIdx.x;
    const int bh = blockIdx.y;
    const int b = bh >> 3, h = bh & 7;
    const int tid = threadIdx.x;

    __shared__ __align__(16) float sq[16][68];
    __shared__ __align__(16) float sk[32][68];
    __shared__ float se[16][260];
    __shared__ float rowmax[16];

    {
        int qq = tid >> 4, c4 = tid & 15;
        float4 v = *(const float4*)(Qs + (size_t)(b*SSq + qq)*Dd + h*DH + c4*4);
        *(float4*)&sq[qq][c4*4] = v;
    }
    __syncthreads();

    const int key0 = chunk * CH;
    for (int t = 0; t < 9; t++) {
        int cnt = min(32, CH - t*32);
        for (int i = tid; i < cnt*16; i += 256) {
            int kk = i >> 4, c4 = i & 15;
            int n = key0 + t*32 + kk;
            const float* kp = (n < SMf)
                ? Ktf + (size_t)(b*SMf + n)*Dd + h*DH
                : Ksp + (size_t)(b*KSn + n - SMf)*Dd + h*DH;
            *(float4*)&sk[kk][c4*4] = *(const float4*)(kp + c4*4);
        }
        __syncthreads();
        for (int p = tid; p < cnt*16; p += 256) {
            int qq = p & 15, kk = p >> 4;
            const float4* qp = (const float4*)sq[qq];
            const float4* kp = (const float4*)sk[kk];
            float acc = 0.f;
#pragma unroll
            for (int c = 0; c < 16; c++) {
                float4 av = qp[c], bv = kp[c];
                acc += av.x*bv.x + av.y*bv.y + av.z*bv.z + av.w*bv.w;
            }
            int n = key0 + t*32 + kk;
            int mv = (n < SMf) ? mt[b*SMf + n] : ms[b*KSn + n - SMf];
            se[qq][t*32 + kk] = acc * SCALE + (mv ? 0.f : -1e30f);
        }
        __syncthreads();
    }

    const int q = tid >> 4, l = tid & 15;
    float lm = -1e38f;
    for (int j = l; j < CH; j += 16) lm = fmaxf(lm, se[q][j]);
#pragma unroll
    for (int o = 8; o > 0; o >>= 1)
        lm = fmaxf(lm, __shfl_xor_sync(0xffffffffu, lm, o));
    if (l == 0) rowmax[q] = lm;
    __syncthreads();
    const float rm = rowmax[q];
    float ls = 0.f;
    const size_t wbase = ((size_t)bh*SSq + q) * (size_t)NKEY + key0;
    for (int j = l; j < CH; j += 16) {
        float e = __expf(se[q][j] - rm);
        se[q][j] = e;
        w_s[wbase + j] = e;
        ls += e;
    }
#pragma unroll
    for (int o = 8; o > 0; o >>= 1)
        ls += __shfl_xor_sync(0xffffffffu, ls, o);
    if (l == 0) {
        int si = (bh*16 + chunk)*16 + q;
        smax[si] = rm; ssum[si] = ls;
    }
    __syncthreads();

    const int grp = tid >> 6, d = tid & 63;
    float acc[16];
#pragma unroll
    for (int i = 0; i < 16; i++) acc[i] = 0.f;
    for (int j = grp; j < CH; j += 4) {
        int n = key0 + j;
        const float* vp = (n < SMf)
            ? Vtf + (size_t)(b*SMf + n)*Dd + h*DH
            : Vsp + (size_t)(b*KSn + n - SMf)*Dd + h*DH;
        float vv = vp[d];
#pragma unroll
        for (int qq = 0; qq < 16; qq++) acc[qq] += se[qq][j] * vv;
    }
    const size_t pb = ((size_t)((bh*16 + chunk)*4 + grp) * 16) * 64 + d;
#pragma unroll
    for (int qq = 0; qq < 16; qq++)
        pout[pb + (size_t)qq*64] = acc[qq];
}

// ---------------------------------------------------------------------------
// Static attention pass 2 (unchanged)
// ---------------------------------------------------------------------------
__global__ __launch_bounds__(128) void static_pass2(
    const float* __restrict__ smax, const float* __restrict__ ssum,
    const float* __restrict__ pout, float* __restrict__ w_s,
    float* __restrict__ qkvs)
{
    const int q = blockIdx.x & 15;
    const int bh = blockIdx.x >> 4;
    const int b = bh >> 3, h = bh & 7;
    const int tid = threadIdx.x;

    __shared__ float fac[16];

    float gmax = -1e38f;
#pragma unroll
    for (int c = 0; c < 16; c++)
        gmax = fmaxf(gmax, smax[(bh*16 + c)*16 + q]);
    float Z = 0.f;
#pragma unroll
    for (int c = 0; c < 16; c++)
        Z += ssum[(bh*16 + c)*16 + q] * __expf(smax[(bh*16 + c)*16 + q] - gmax);
    const float invZ = 1.f / Z;
    if (tid < 16)
        fac[tid] = __expf(smax[(bh*16 + tid)*16 + q] - gmax) * invZ;
    __syncthreads();

    if (tid < 64) {
        float o = 0.f;
#pragma unroll
        for (int c = 0; c < 16; c++) {
            float s4 = 0.f;
            size_t pb = ((size_t)((bh*16 + c)*4) * 16 + q) * 64 + tid;
#pragma unroll
            for (int g = 0; g < 4; g++) s4 += pout[pb + (size_t)g*16*64];
            o += fac[c] * s4;
        }
        qkvs[(size_t)(b*SSq + q)*Dd + h*DH + tid] = o;
    }

    const size_t wbase = ((size_t)bh*SSq + q) * (size_t)NKEY;
    for (int n = tid; n < NKEY; n += 128)
        w_s[wbase + n] *= fac[n / CH];
}

// ---------------------------------------------------------------------------
extern "C" void kernel_launch(void* const* d_in, const int* in_sizes, int n_in,
                              void* d_out, int out_size)
{
    (void)in_sizes; (void)n_in; (void)out_size;
    const float* q_t = (const float*)d_in[0];
    const float* k_t = (const float*)d_in[1];
    const float* v_t = (const float*)d_in[2];
    const float* q_s = (const float*)d_in[3];
    const float* k_s = (const float*)d_in[4];
    const float* v_s = (const float*)d_in[5];
    const int*   m_t = (const int*)d_in[6];
    const int*   m_s = (const int*)d_in[7];
    const float* Wq = (const float*)d_in[8];
    const float* bq = (const float*)d_in[9];
    const float* Wk = (const float*)d_in[10];
    const float* bk = (const float*)d_in[11];
    const float* Wv = (const float*)d_in[12];
    const float* bv = (const float*)d_in[13];
    const float* Wo = (const float*)d_in[14];
    const float* bo = (const float*)d_in[15];

    float* out   = (float*)d_out;
    float* out_t = out;
    float* w_t   = out_t + (size_t)Bb*Ss_*Mm*Dd;
    float* out_s = w_t + (size_t)Bb*Hh*Ss_*Mm*(Mm+KSn);
    float* w_s   = out_s + (size_t)Bb*SSq*Dd;

    float *p_qt, *p_kt, *p_vt, *p_qkvt, *p_qs, *p_ks, *p_vs, *p_qkvs;
    float *p_smax, *p_ssum, *p_pout;
    bf16 *p_wth, *p_wtl;
    cudaGetSymbolAddress((void**)&p_qt,   g_qt);
    cudaGetSymbolAddress((void**)&p_kt,   g_kt);
    cudaGetSymbolAddress((void**)&p_vt,   g_vt);
    cudaGetSymbolAddress((void**)&p_qkvt, g_qkvt);
    cudaGetSymbolAddress((void**)&p_qs,   g_qs);
    cudaGetSymbolAddress((void**)&p_ks,   g_ks);
    cudaGetSymbolAddress((void**)&p_vs,   g_vs);
    cudaGetSymbolAddress((void**)&p_qkvs, g_qkvs);
    cudaGetSymbolAddress((void**)&p_wth,  g_wth);
    cudaGetSymbolAddress((void**)&p_wtl,  g_wtl);
    cudaGetSymbolAddress((void**)&p_smax, g_smax);
    cudaGetSymbolAddress((void**)&p_ssum, g_ssum);
    cudaGetSymbolAddress((void**)&p_pout, g_pout);

    const size_t WSZ = (size_t)Dd * Dd;
    bf16* wqh = p_wth + 0*WSZ; bf16* wql = p_wtl + 0*WSZ;
    bf16* wkh = p_wth + 1*WSZ; bf16* wkl = p_wtl + 1*WSZ;
    bf16* wvh = p_wth + 2*WSZ; bf16* wvl = p_wtl + 2*WSZ;
    bf16* woh = p_wth + 3*WSZ; bf16* wol = p_wtl + 3*WSZ;

    cudaFuncSetAttribute(mma_gemm, cudaFuncAttributeMaxDynamicSharedMemorySize,
                         DSMEM_B);

    // 1) weight transpose+split
    WArgs wa;
    wa.W[0] = Wq; wa.Wh[0] = wqh; wa.Wl[0] = wql;
    wa.W[1] = Wk; wa.Wh[1] = wkh; wa.Wl[1] = wkl;
    wa.W[2] = Wv; wa.Wh[2] = wvh; wa.Wl[2] = wvl;
    wa.W[3] = Wo; wa.Wh[3] = woh; wa.Wl[3] = wol;
    wsplit_kernel<<<dim3(16,16,4), dim3(32,8)>>>(wa);

    // 2) all six input projections in one batched launch
    GBatch pb;
    pb.g[0] = { q_t, wqh, wql, bq, p_qt, TROWS };
    pb.g[1] = { k_t, wkh, wkl, bk, p_kt, TROWS };
    pb.g[2] = { v_t, wvh, wvl, bv, p_vt, TROWS };
    pb.g[3] = { q_s, wqh, wql, bq, p_qs, SROWS };
    pb.g[4] = { k_s, wkh, wkl, bk, p_ks, SROWS };
    pb.g[5] = { v_s, wvh, wvl, bv, p_vs, SROWS };
    mma_gemm<<<dim3(4, 256, 6), 256, DSMEM_B>>>(pb);

    // 3) attention
    temporal_attn_kernel<<<Bb*Hh*Ss_, 64>>>(p_qt, p_kt, p_vt, p_ks, p_vs,
                                            m_t, m_s, w_t, p_qkvt);
    static_pass1<<<dim3(16, 64), 256>>>(p_qs, p_kt, p_vt, p_ks, p_vs,
                                        m_t, m_s, w_s, p_smax, p_ssum, p_pout);
    static_pass2<<<1024, 128>>>(p_smax, p_ssum, p_pout, w_s, p_qkvs);

    // 4) output projections — grid.z = 2 ONLY (g[2..5] were duplicates of
    //    g[0] since round 2: the big output GEMM was computed 5x!)
    GBatch ob;
    ob.g[0] = { p_qkvt, woh, wol, bo, out_t, TROWS };
    ob.g[1] = { p_qkvs, woh, wol, bo, out_s, SROWS };
    ob.g[2] = ob.g[1]; ob.g[3] = ob.g[1]; ob.g[4] = ob.g[1]; ob.g[5] = ob.g[1];
    mma_gemm<<<dim3(4, 256, 2), 256, DSMEM_B>>>(ob);
}

// round 14
// speedup vs baseline: 1.0065x; 1.0065x over previous
#include <cuda_runtime.h>
#include <cuda_bf16.h>
#include <cstdint>
#include <math.h>

typedef __nv_bfloat16 bf16;

// Problem constants
#define Bb 8
#define Ss_ 512
#define Mm 8
#define Dd 512
#define Hh 8
#define DH 64
#define SSq 16
#define KSn 16
#define SMf 4096
#define NKEY (SMf + KSn)
#define SCALE 0.125f
#define CH 257

#define TROWS (Bb*Ss_*Mm)  // 32768
#define SROWS (Bb*SSq)     // 128

// ---------------------------------------------------------------------------
// Scratch (device globals — no allocation allowed)
// ---------------------------------------------------------------------------
__device__ float g_qt[(size_t)TROWS*Dd];
__device__ float g_kt[(size_t)TROWS*Dd];
__device__ float g_vt[(size_t)TROWS*Dd];
__device__ float g_qkvt[(size_t)TROWS*Dd];
__device__ float g_qs[(size_t)SROWS*Dd];
__device__ float g_ks[(size_t)SROWS*Dd];
__device__ float g_vs[(size_t)SROWS*Dd];
__device__ float g_qkvs[(size_t)SROWS*Dd];
__device__ bf16 g_wth[4][(size_t)Dd*Dd];
__device__ bf16 g_wtl[4][(size_t)Dd*Dd];
__device__ float g_smax[64*16*16];
__device__ float g_ssum[64*16*16];
__device__ float g_pout[(size_t)64*16*4*16*64];

// ---------------------------------------------------------------------------
__device__ __forceinline__ uint32_t bf2u(__nv_bfloat162 v) {
    return *reinterpret_cast<uint32_t*>(&v);
}
__device__ __forceinline__ void split2(float x, float y, uint32_t& h, uint32_t& l) {
    __nv_bfloat162 H = __floats2bfloat162_rn(x, y);
    float hx = __bfloat162float(H.x), hy = __bfloat162float(H.y);
    __nv_bfloat162 L = __floats2bfloat162_rn(x - hx, y - hy);
    h = bf2u(H); l = bf2u(L);
}

__device__ __forceinline__ void mma16816(float* c,
    uint32_t a0, uint32_t a1, uint32_t a2, uint32_t a3,
    uint32_t b0, uint32_t b1)
{
    asm volatile(
        "mma.sync.aligned.m16n8k16.row.col.f32.bf16.bf16.f32 "
        "{%0,%1,%2,%3}, {%4,%5,%6,%7}, {%8,%9}, {%0,%1,%2,%3};"
        : "+f"(c[0]), "+f"(c[1]), "+f"(c[2]), "+f"(c[3])
        : "r"(a0), "r"(a1), "r"(a2), "r"(a3), "r"(b0), "r"(b1));
}

__device__ __forceinline__ void ldsm4(uint32_t* r, uint32_t addr) {
    asm volatile(
        "ldmatrix.sync.aligned.m8n8.x4.shared.b16 {%0,%1,%2,%3}, [%4];"
        : "=r"(r[0]), "=r"(r[1]), "=r"(r[2]), "=r"(r[3]) : "r"(addr));
}

__device__ __forceinline__ void cp16(uint32_t smem_dst, const void* gsrc) {
    asm volatile("cp.async.cg.shared.global [%0], [%1], 16;"
                 :: "r"(smem_dst), "l"(gsrc));
}
__device__ __forceinline__ void cp_commit() {
    asm volatile("cp.async.commit_group;" ::: "memory");
}
template<int N>
__device__ __forceinline__ void cp_wait() {
    asm volatile("cp.async.wait_group %0;" :: "n"(N) : "memory");
}

// ---------------------------------------------------------------------------
// Weight transpose + split
// ---------------------------------------------------------------------------
struct WArgs { const float* W[4]; bf16* Wh[4]; bf16* Wl[4]; };

__global__ __launch_bounds__(256) void wsplit_kernel(WArgs a) {
    const int z = blockIdx.z;
    const float* W = a.W[z];
    bf16* Wh = a.Wh[z];
    bf16* Wl = a.Wl[z];
    __shared__ float t[32][33];
    const int x0 = blockIdx.x * 32, y0 = blockIdx.y * 32;
    const int tx = threadIdx.x, ty = threadIdx.y;
#pragma unroll
    for (int i = ty; i < 32; i += 8)
        t[i][tx] = W[(size_t)(y0 + i) * Dd + x0 + tx];
    __syncthreads();
#pragma unroll
    for (int i = ty; i < 32; i += 8) {
        float v = t[tx][i];
        bf16 h = __float2bfloat16(v);
        bf16 l = __float2bfloat16(v - __bfloat162float(h));
        size_t o = (size_t)(x0 + i) * Dd + y0 + tx;
        Wh[o] = h; Wl[o] = l;
    }
}

// ---------------------------------------------------------------------------
// MMA GEMM (round-10 version — best measured; unchanged)
// ---------------------------------------------------------------------------
struct GB { const float* A; const bf16* Wh; const bf16* Wl;
            const float* bias; float* C; int rows; };
struct GBatch { GB g[6]; };

#define BK 32
#define KPAD 40
#define ARR_B   (128*KPAD*2)
#define STAGE_B (4*ARR_B)
#define DSMEM_B (2*STAGE_B)

__global__ __launch_bounds__(256, 2) void mma_gemm(GBatch batch) {
    const GB a = batch.g[blockIdx.z];
    const int brow = blockIdx.y * 128;
    if (brow >= a.rows) return;
    const int bcol = blockIdx.x * 128;

    extern __shared__ __align__(16) char dsm[];
    bf16* const sb = (bf16*)dsm;
    uint32_t smem_u32;
    {
        uint64_t t = __cvta_generic_to_shared(dsm);
        smem_u32 = (uint32_t)t;
    }

    const int tid = threadIdx.x;
    const int wid = tid >> 5, lane = tid & 31;
    const int warpM = wid & 3;
    const int warpN = wid >> 2;
    const int ra = lane >> 2;
    const int tk = (lane & 3) * 2;

    const int g8 = lane >> 3;
    const int r8 = lane & 7;
    const uint32_t a_ld_off = (uint32_t)((warpM*32 + (g8 & 1)*8 + r8) * KPAD
                                         + (g8 >> 1)*8) * 2;
    const uint32_t w_ld_off = (uint32_t)((warpN*64 + (g8 >> 1)*8 + r8) * KPAD
                                         + (g8 & 1)*8) * 2;

    const int ar = tid >> 1;
    const int ac = (tid & 1) * 4;
    const float* gA = a.A + (size_t)(brow + ar) * Dd + ac * 4;
    const int warr = tid >> 7;
    const int wr = tid & 127;
    const bf16* gW = (warr ? a.Wl : a.Wh) + (size_t)(bcol + wr) * Dd;
    const uint32_t wdst0 = smem_u32 + (2 + warr) * ARR_B + wr * (KPAD*2);

    float acc[2][8][4];
#pragma unroll
    for (int mi = 0; mi < 2; mi++)
#pragma unroll
        for (int ni = 0; ni < 8; ni++)
#pragma unroll
            for (int j = 0; j < 4; j++) acc[mi][ni][j] = 0.f;

    float4 pA[4];
#pragma unroll
    for (int i = 0; i < 4; i++) pA[i] = *(const float4*)(gA + i * 4);
#pragma unroll
    for (int q = 0; q < 4; q++)
        cp16(wdst0 + q * 16, gW + q * 8);
    cp_commit();

    for (int it = 0; it < 16; it++) {
        const int cur = it & 1;
        bf16* const Ah = sb + cur * (STAGE_B/2);
        bf16* const Al = Ah + ARR_B/2;
        const uint32_t stage = smem_u32 + cur * STAGE_B;

#pragma unroll
        for (int i = 0; i < 4; i++) {
            float4 v = pA[i];
            uint32_t h0, l0, h1, l1;
            split2(v.x, v.y, h0, l0);
            split2(v.z, v.w, h1, l1);
            *(uint2*)(Ah + ar*KPAD + (ac + i)*4) = make_uint2(h0, h1);
            *(uint2*)(Al + ar*KPAD + (ac + i)*4) = make_uint2(l0, l1);
        }

        if (it + 1 < 16) {
            const int k1 = (it + 1) * BK;
#pragma unroll
            for (int i = 0; i < 4; i++)
                pA[i] = *(const float4*)(gA + k1 + i * 4);
            const uint32_t wd = wdst0 + (cur ^ 1) * STAGE_B;
#pragma unroll
            for (int q = 0; q < 4; q++)
                cp16(wd + q * 16, gW + k1 + q * 8);
            cp_commit();
            cp_wait<1>();
        } else {
            cp_wait<0>();
        }
        __syncthreads();

#pragma unroll
        for (int ks = 0; ks < 2; ks++) {
            const uint32_t kso = ks * 32;
            uint32_t ah[2][4], al[2][4];
#pragma unroll
            for (int mi = 0; mi < 2; mi++) {
                const uint32_t ao = a_ld_off + mi * (16*KPAD*2) + kso;
                ldsm4(ah[mi], stage + ao);
                ldsm4(al[mi], stage + ARR_B + ao);
            }
#pragma unroll
            for (int np = 0; np < 4; np++) {
                uint32_t wh[4], wl[4];
                const uint32_t wo = w_ld_off + np * (16*KPAD*2) + kso;
                ldsm4(wh, stage + 2*ARR_B + wo);
                ldsm4(wl, stage + 3*ARR_B + wo);
#pragma unroll
                for (int mi = 0; mi < 2; mi++) {
                    float* c0 = acc[mi][2*np];
                    float* c1 = acc[mi][2*np + 1];
                    mma16816(c0, ah[mi][0], ah[mi][1], ah[mi][2], ah[mi][3], wh[0], wh[1]);
                    mma16816(c0, ah[mi][0], ah[mi][1], ah[mi][2], ah[mi][3], wl[0], wl[1]);
                    mma16816(c0, al[mi][0], al[mi][1], al[mi][2], al[mi][3], wh[0], wh[1]);
                    mma16816(c1, ah[mi][0], ah[mi][1], ah[mi][2], ah[mi][3], wh[2], wh[3]);
                    mma16816(c1, ah[mi][0], ah[mi][1], ah[mi][2], ah[mi][3], wl[2], wl[3]);
                    mma16816(c1, al[mi][0], al[mi][1], al[mi][2], al[mi][3], wh[2], wh[3]);
                }
            }
        }
        __syncthreads();
    }

#pragma unroll
    for (int mi = 0; mi < 2; mi++) {
        int row0 = brow + warpM * 32 + mi * 16 + ra;
#pragma unroll
        for (int ni = 0; ni < 8; ni++) {
            int col = bcol + warpN * 64 + ni * 8 + tk;
            float bx = a.bias[col], by = a.bias[col + 1];
            float2 o0 = make_float2(acc[mi][ni][0] + bx, acc[mi][ni][1] + by);
            float2 o1 = make_float2(acc[mi][ni][2] + bx, acc[mi][ni][3] + by);
            *(float2*)(a.C + (size_t)row0 * Dd + col) = o0;
            *(float2*)(a.C + (size_t)(row0 + 8) * Dd + col) = o1;
        }
    }
}

// ---------------------------------------------------------------------------
// Temporal attention v5: 256 threads = 4 groups of 64, each group = one s.
// ks tile shared across the 4 s values (loaded once per block).
// ---------------------------------------------------------------------------
#define QP 68

__global__ __launch_bounds__(256) void temporal_attn_kernel(
    const float* __restrict__ Qt, const float* __restrict__ Kt,
    const float* __restrict__ Vt, const float* __restrict__ Ksp,
    const float* __restrict__ Vsp, const int* __restrict__ mt,
    const int* __restrict__ ms, float* __restrict__ w_t,
    float* __restrict__ qkvt)
{
    const int bx = blockIdx.x;              // B*H*(S/4) = 8192
    const int g  = threadIdx.x >> 6;        // 0..3
    const int d  = threadIdx.x & 63;
    const int s4 = bx % (Ss_/4);
    const int h  = (bx / (Ss_/4)) % Hh;
    const int b  = bx / ((Ss_/4) * Hh);
    const int s  = s4 * 4 + g;

    __shared__ __align__(16) float q[4][Mm][QP], k[4][Mm][QP];
    __shared__ __align__(16) float ks[KSn][QP];
    __shared__ float sc[4][Mm][Mm+KSn];

    const size_t base_t = ((size_t)(b*Ss_ + s) * Mm) * Dd + (size_t)h * DH;
#pragma unroll
    for (int m = 0; m < Mm; m++) {
        q[g][m][d] = Qt[base_t + (size_t)m*Dd + d];
        k[g][m][d] = Kt[base_t + (size_t)m*Dd + d];
    }
    const size_t base_s = (size_t)b*KSn*Dd + (size_t)h*DH;
#pragma unroll
    for (int i = 0; i < 4; i++) {
        int n = g * 4 + i;
        ks[n][d] = Ksp[base_s + (size_t)n*Dd + d];
    }
    __syncthreads();

    // scores: 192 dots per group, 3 per thread, float4 smem reads
    for (int e = d; e < Mm*(Mm+KSn); e += 64) {
        int m = e / (Mm+KSn), n = e % (Mm+KSn);
        const float4* kp = (const float4*)((n < Mm) ? k[g][n] : ks[n-Mm]);
        const float4* qp = (const float4*)q[g][m];
        float acc = 0.f;
#pragma unroll
        for (int c = 0; c < DH/4; c++) {
            float4 av = qp[c], bv = kp[c];
            acc += av.x*bv.x + av.y*bv.y + av.z*bv.z + av.w*bv.w;
        }
        int maskv = (n < Mm) ? mt[(b*Ss_+s)*Mm + n] : ms[b*KSn + (n-Mm)];
        sc[g][m][n] = acc * SCALE + (maskv ? 0.f : -1e30f);
    }
    __syncthreads();

    // softmax: per group, 8 lane-groups of 8
    {
        const int m = d >> 3;
        const int l = d & 7;
        float s0 = sc[g][m][l], s1 = sc[g][m][l+8], s2 = sc[g][m][l+16];
        float lm = fmaxf(s0, fmaxf(s1, s2));
#pragma unroll
        for (int o = 4; o > 0; o >>= 1)
            lm = fmaxf(lm, __shfl_xor_sync(0xffffffffu, lm, o, 8));
        float e0 = __expf(s0 - lm), e1 = __expf(s1 - lm), e2 = __expf(s2 - lm);
        float ls = e0 + e1 + e2;
#pragma unroll
        for (int o = 4; o > 0; o >>= 1)
            ls += __shfl_xor_sync(0xffffffffu, ls, o, 8);
        const float inv = 1.f / ls;
        e0 *= inv; e1 *= inv; e2 *= inv;
        sc[g][m][l] = e0; sc[g][m][l+8] = e1; sc[g][m][l+16] = e2;
        const size_t wbase = ((((size_t)(b*Hh+h)*Ss_ + s) * Mm) + m) * (Mm+KSn);
        w_t[wbase + l]      = e0;
        w_t[wbase + l + 8]  = e1;
        w_t[wbase + l + 16] = e2;
    }
    __syncthreads();

    // P*V: V/Vs from global, 8 register accumulators per thread
    {
        float accv[Mm];
#pragma unroll
        for (int m = 0; m < Mm; m++) accv[m] = 0.f;
#pragma unroll
        for (int n = 0; n < Mm; n++) {
            float vv = Vt[base_t + (size_t)n*Dd + d];
#pragma unroll
            for (int m = 0; m < Mm; m++) accv[m] += sc[g][m][n] * vv;
        }
#pragma unroll
        for (int n = 0; n < KSn; n++) {
            float vv = Vsp[base_s + (size_t)n*Dd + d];
#pragma unroll
            for (int m = 0; m < Mm; m++) accv[m] += sc[g][m][Mm+n] * vv;
        }
#pragma unroll
        for (int m = 0; m < Mm; m++)
            qkvt[base_t + (size_t)m*Dd + d] = accv[m];
    }
}

// ---------------------------------------------------------------------------
// Static attention pass 1: launch_bounds(256,4) — occupancy was reg-limited
// to 3 blocks/SM at 80 regs (occ 32%, issue 36% = warp-starved).
// ---------------------------------------------------------------------------
__global__ __launch_bounds__(256, 4) void static_pass1(
    const float* __restrict__ Qs, const float* __restrict__ Ktf,
    const float* __restrict__ Vtf, const float* __restrict__ Ksp,
    const float* __restrict__ Vsp, const int* __restrict__ mt,
    const int* __restrict__ ms, float* __restrict__ w_s,
    float* __restrict__ smax, float* __restrict__ ssum,
    float* __restrict__ pout)
{
    const int chunk = blockIdx.x;
    const int bh = blockIdx.y;
    const int b = bh >> 3, h = bh & 7;
    const int tid = threadIdx.x;

    __shared__ __align__(16) float sq[16][68];
    __shared__ __align__(16) float sk[32][68];
    __shared__ float se[16][260];
    __shared__ float rowmax[16];

    {
        int qq = tid >> 4, c4 = tid & 15;
        float4 v = *(const float4*)(Qs + (size_t)(b*SSq + qq)*Dd + h*DH + c4*4);
        *(float4*)&sq[qq][c4*4] = v;
    }
    __syncthreads();

    const int key0 = chunk * CH;
    for (int t = 0; t < 9; t++) {
        int cnt = min(32, CH - t*32);
        for (int i = tid; i < cnt*16; i += 256) {
            int kk = i >> 4, c4 = i & 15;
            int n = key0 + t*32 + kk;
            const float* kp = (n < SMf)
                ? Ktf + (size_t)(b*SMf + n)*Dd + h*DH
                : Ksp + (size_t)(b*KSn + n - SMf)*Dd + h*DH;
            *(float4*)&sk[kk][c4*4] = *(const float4*)(kp + c4*4);
        }
        __syncthreads();
        for (int p = tid; p < cnt*16; p += 256) {
            int qq = p & 15, kk = p >> 4;
            const float4* qp = (const float4*)sq[qq];
            const float4* kp = (const float4*)sk[kk];
            float acc = 0.f;
#pragma unroll
            for (int c = 0; c < 16; c++) {
                float4 av = qp[c], bv = kp[c];
                acc += av.x*bv.x + av.y*bv.y + av.z*bv.z + av.w*bv.w;
            }
            int n = key0 + t*32 + kk;
            int mv = (n < SMf) ? mt[b*SMf + n] : ms[b*KSn + n - SMf];
            se[qq][t*32 + kk] = acc * SCALE + (mv ? 0.f : -1e30f);
        }
        __syncthreads();
    }

    const int q = tid >> 4, l = tid & 15;
    float lm = -1e38f;
    for (int j = l; j < CH; j += 16) lm = fmaxf(lm, se[q][j]);
#pragma unroll
    for (int o = 8; o > 0; o >>= 1)
        lm = fmaxf(lm, __shfl_xor_sync(0xffffffffu, lm, o));
    if (l == 0) rowmax[q] = lm;
    __syncthreads();
    const float rm = rowmax[q];
    float ls = 0.f;
    const size_t wbase = ((size_t)bh*SSq + q) * (size_t)NKEY + key0;
    for (int j = l; j < CH; j += 16) {
        float e = __expf(se[q][j] - rm);
        se[q][j] = e;
        w_s[wbase + j] = e;
        ls += e;
    }
#pragma unroll
    for (int o = 8; o > 0; o >>= 1)
        ls += __shfl_xor_sync(0xffffffffu, ls, o);
    if (l == 0) {
        int si = (bh*16 + chunk)*16 + q;
        smax[si] = rm; ssum[si] = ls;
    }
    __syncthreads();

    const int grp = tid >> 6, d = tid & 63;
    float acc[16];
#pragma unroll
    for (int i = 0; i < 16; i++) acc[i] = 0.f;
    for (int j = grp; j < CH; j += 4) {
        int n = key0 + j;
        const float* vp = (n < SMf)
            ? Vtf + (size_t)(b*SMf + n)*Dd + h*DH
            : Vsp + (size_t)(b*KSn + n - SMf)*Dd + h*DH;
        float vv = vp[d];
#pragma unroll
        for (int qq = 0; qq < 16; qq++) acc[qq] += se[qq][j] * vv;
    }
    const size_t pb = ((size_t)((bh*16 + chunk)*4 + grp) * 16) * 64 + d;
#pragma unroll
    for (int qq = 0; qq < 16; qq++)
        pout[pb + (size_t)qq*64] = acc[qq];
}

// ---------------------------------------------------------------------------
// Static attention pass 2 (unchanged)
// ---------------------------------------------------------------------------
__global__ __launch_bounds__(128) void static_pass2(
    const float* __restrict__ smax, const float* __restrict__ ssum,
    const float* __restrict__ pout, float* __restrict__ w_s,
    float* __restrict__ qkvs)
{
    const int q = blockIdx.x & 15;
    const int bh = blockIdx.x >> 4;
    const int b = bh >> 3, h = bh & 7;
    const int tid = threadIdx.x;

    __shared__ float fac[16];

    float gmax = -1e38f;
#pragma unroll
    for (int c = 0; c < 16; c++)
        gmax = fmaxf(gmax, smax[(bh*16 + c)*16 + q]);
    float Z = 0.f;
#pragma unroll
    for (int c = 0; c < 16; c++)
        Z += ssum[(bh*16 + c)*16 + q] * __expf(smax[(bh*16 + c)*16 + q] - gmax);
    const float invZ = 1.f / Z;
    if (tid < 16)
        fac[tid] = __expf(smax[(bh*16 + tid)*16 + q] - gmax) * invZ;
    __syncthreads();

    if (tid < 64) {
        float o = 0.f;
#pragma unroll
        for (int c = 0; c < 16; c++) {
            float s4 = 0.f;
            size_t pb = ((size_t)((bh*16 + c)*4) * 16 + q) * 64 + tid;
#pragma unroll
            for (int g = 0; g < 4; g++) s4 += pout[pb + (size_t)g*16*64];
            o += fac[c] * s4;
        }
        qkvs[(size_t)(b*SSq + q)*Dd + h*DH + tid] = o;
    }

    const size_t wbase = ((size_t)bh*SSq + q) * (size_t)NKEY;
    for (int n = tid; n < NKEY; n += 128)
        w_s[wbase + n] *= fac[n / CH];
}

// ---------------------------------------------------------------------------
extern "C" void kernel_launch(void* const* d_in, const int* in_sizes, int n_in,
                              void* d_out, int out_size)
{
    (void)in_sizes; (void)n_in; (void)out_size;
    const float* q_t = (const float*)d_in[0];
    const float* k_t = (const float*)d_in[1];
    const float* v_t = (const float*)d_in[2];
    const float* q_s = (const float*)d_in[3];
    const float* k_s = (const float*)d_in[4];
    const float* v_s = (const float*)d_in[5];
    const int*   m_t = (const int*)d_in[6];
    const int*   m_s = (const int*)d_in[7];
    const float* Wq = (const float*)d_in[8];
    const float* bq = (const float*)d_in[9];
    const float* Wk = (const float*)d_in[10];
    const float* bk = (const float*)d_in[11];
    const float* Wv = (const float*)d_in[12];
    const float* bv = (const float*)d_in[13];
    const float* Wo = (const float*)d_in[14];
    const float* bo = (const float*)d_in[15];

    float* out   = (float*)d_out;
    float* out_t = out;
    float* w_t   = out_t + (size_t)Bb*Ss_*Mm*Dd;
    float* out_s = w_t + (size_t)Bb*Hh*Ss_*Mm*(Mm+KSn);
    float* w_s   = out_s + (size_t)Bb*SSq*Dd;

    float *p_qt, *p_kt, *p_vt, *p_qkvt, *p_qs, *p_ks, *p_vs, *p_qkvs;
    float *p_smax, *p_ssum, *p_pout;
    bf16 *p_wth, *p_wtl;
    cudaGetSymbolAddress((void**)&p_qt,   g_qt);
    cudaGetSymbolAddress((void**)&p_kt,   g_kt);
    cudaGetSymbolAddress((void**)&p_vt,   g_vt);
    cudaGetSymbolAddress((void**)&p_qkvt, g_qkvt);
    cudaGetSymbolAddress((void**)&p_qs,   g_qs);
    cudaGetSymbolAddress((void**)&p_ks,   g_ks);
    cudaGetSymbolAddress((void**)&p_vs,   g_vs);
    cudaGetSymbolAddress((void**)&p_qkvs, g_qkvs);
    cudaGetSymbolAddress((void**)&p_wth,  g_wth);
    cudaGetSymbolAddress((void**)&p_wtl,  g_wtl);
    cudaGetSymbolAddress((void**)&p_smax, g_smax);
    cudaGetSymbolAddress((void**)&p_ssum, g_ssum);
    cudaGetSymbolAddress((void**)&p_pout, g_pout);

    const size_t WSZ = (size_t)Dd * Dd;
    bf16* wqh = p_wth + 0*WSZ; bf16* wql = p_wtl + 0*WSZ;
    bf16* wkh = p_wth + 1*WSZ; bf16* wkl = p_wtl + 1*WSZ;
    bf16* wvh = p_wth + 2*WSZ; bf16* wvl = p_wtl + 2*WSZ;
    bf16* woh = p_wth + 3*WSZ; bf16* wol = p_wtl + 3*WSZ;

    cudaFuncSetAttribute(mma_gemm, cudaFuncAttributeMaxDynamicSharedMemorySize,
                         DSMEM_B);

    // 1) weight transpose+split
    WArgs wa;
    wa.W[0] = Wq; wa.Wh[0] = wqh; wa.Wl[0] = wql;
    wa.W[1] = Wk; wa.Wh[1] = wkh; wa.Wl[1] = wkl;
    wa.W[2] = Wv; wa.Wh[2] = wvh; wa.Wl[2] = wvl;
    wa.W[3] = Wo; wa.Wh[3] = woh; wa.Wl[3] = wol;
    wsplit_kernel<<<dim3(16,16,4), dim3(32,8)>>>(wa);

    // 2) all six input projections in one batched launch
    GBatch pb;
    pb.g[0] = { q_t, wqh, wql, bq, p_qt, TROWS };
    pb.g[1] = { k_t, wkh, wkl, bk, p_kt, TROWS };
    pb.g[2] = { v_t, wvh, wvl, bv, p_vt, TROWS };
    pb.g[3] = { q_s, wqh, wql, bq, p_qs, SROWS };
    pb.g[4] = { k_s, wkh, wkl, bk, p_ks, SROWS };
    pb.g[5] = { v_s, wvh, wvl, bv, p_vs, SROWS };
    mma_gemm<<<dim3(4, 256, 6), 256, DSMEM_B>>>(pb);

    // 3) attention
    temporal_attn_kernel<<<Bb*Hh*(Ss_/4), 256>>>(p_qt, p_kt, p_vt, p_ks, p_vs,
                                                 m_t, m_s, w_t, p_qkvt);
    static_pass1<<<dim3(16, 64), 256>>>(p_qs, p_kt, p_vt, p_ks, p_vs,
                                        m_t, m_s, w_s, p_smax, p_ssum, p_pout);
    static_pass2<<<1024, 128>>>(p_smax, p_ssum, p_pout, w_s, p_qkvs);

    // 4) output projections (2 real GEMMs)
    GBatch ob;
    ob.g[0] = { p_qkvt, woh, wol, bo, out_t, TROWS };
    ob.g[1] = { p_qkvs, woh, wol, bo, out_s, SROWS };
    ob.g[2] = ob.g[1]; ob.g[3] = ob.g[1]; ob.g[4] = ob.g[1]; ob.g[5] = ob.g[1];
    mma_gemm<<<dim3(4, 256, 2), 256, DSMEM_B>>>(ob);
}

// round 15
// speedup vs baseline: 1.0118x; 1.0052x over previous
#include <cuda_runtime.h>
#include <cuda_bf16.h>
#include <cstdint>
#include <math.h>

typedef __nv_bfloat16 bf16;

// Problem constants
#define Bb 8
#define Ss_ 512
#define Mm 8
#define Dd 512
#define Hh 8
#define DH 64
#define SSq 16
#define KSn 16
#define SMf 4096
#define NKEY (SMf + KSn)
#define SCALE 0.125f
#define CH 257

#define TROWS (Bb*Ss_*Mm)  // 32768
#define SROWS (Bb*SSq)     // 128

// ---------------------------------------------------------------------------
// Scratch (device globals — no allocation allowed)
// ---------------------------------------------------------------------------
__device__ float g_qt[(size_t)TROWS*Dd];
__device__ float g_kt[(size_t)TROWS*Dd];
__device__ float g_vt[(size_t)TROWS*Dd];
__device__ float g_qkvt[(size_t)TROWS*Dd];
__device__ float g_qs[(size_t)SROWS*Dd];
__device__ float g_ks[(size_t)SROWS*Dd];
__device__ float g_vs[(size_t)SROWS*Dd];
__device__ float g_qkvs[(size_t)SROWS*Dd];
__device__ bf16 g_wth[4][(size_t)Dd*Dd];
__device__ bf16 g_wtl[4][(size_t)Dd*Dd];
__device__ float g_smax[64*16*16];
__device__ float g_ssum[64*16*16];
__device__ float g_pout[(size_t)64*16*4*16*64];

// ---------------------------------------------------------------------------
__device__ __forceinline__ uint32_t bf2u(__nv_bfloat162 v) {
    return *reinterpret_cast<uint32_t*>(&v);
}
__device__ __forceinline__ void split2(float x, float y, uint32_t& h, uint32_t& l) {
    __nv_bfloat162 H = __floats2bfloat162_rn(x, y);
    float hx = __bfloat162float(H.x), hy = __bfloat162float(H.y);
    __nv_bfloat162 L = __floats2bfloat162_rn(x - hx, y - hy);
    h = bf2u(H); l = bf2u(L);
}

__device__ __forceinline__ void mma16816(float* c,
    uint32_t a0, uint32_t a1, uint32_t a2, uint32_t a3,
    uint32_t b0, uint32_t b1)
{
    asm volatile(
        "mma.sync.aligned.m16n8k16.row.col.f32.bf16.bf16.f32 "
        "{%0,%1,%2,%3}, {%4,%5,%6,%7}, {%8,%9}, {%0,%1,%2,%3};"
        : "+f"(c[0]), "+f"(c[1]), "+f"(c[2]), "+f"(c[3])
        : "r"(a0), "r"(a1), "r"(a2), "r"(a3), "r"(b0), "r"(b1));
}

__device__ __forceinline__ void ldsm4(uint32_t* r, uint32_t addr) {
    asm volatile(
        "ldmatrix.sync.aligned.m8n8.x4.shared.b16 {%0,%1,%2,%3}, [%4];"
        : "=r"(r[0]), "=r"(r[1]), "=r"(r[2]), "=r"(r[3]) : "r"(addr));
}

__device__ __forceinline__ void cp16(uint32_t smem_dst, const void* gsrc) {
    asm volatile("cp.async.cg.shared.global [%0], [%1], 16;"
                 :: "r"(smem_dst), "l"(gsrc));
}
__device__ __forceinline__ void cp_commit() {
    asm volatile("cp.async.commit_group;" ::: "memory");
}
template<int N>
__device__ __forceinline__ void cp_wait() {
    asm volatile("cp.async.wait_group %0;" :: "n"(N) : "memory");
}

// ---------------------------------------------------------------------------
// Weight transpose + split
// ---------------------------------------------------------------------------
struct WArgs { const float* W[4]; bf16* Wh[4]; bf16* Wl[4]; };

__global__ __launch_bounds__(256) void wsplit_kernel(WArgs a) {
    const int z = blockIdx.z;
    const float* W = a.W[z];
    bf16* Wh = a.Wh[z];
    bf16* Wl = a.Wl[z];
    __shared__ float t[32][33];
    const int x0 = blockIdx.x * 32, y0 = blockIdx.y * 32;
    const int tx = threadIdx.x, ty = threadIdx.y;
#pragma unroll
    for (int i = ty; i < 32; i += 8)
        t[i][tx] = W[(size_t)(y0 + i) * Dd + x0 + tx];
    __syncthreads();
#pragma unroll
    for (int i = ty; i < 32; i += 8) {
        float v = t[tx][i];
        bf16 h = __float2bfloat16(v);
        bf16 l = __float2bfloat16(v - __bfloat162float(h));
        size_t o = (size_t)(x0 + i) * Dd + y0 + tx;
        Wh[o] = h; Wl[o] = l;
    }
}

// ---------------------------------------------------------------------------
// MMA GEMM (round-10 version — best measured; unchanged)
// ---------------------------------------------------------------------------
struct GB { const float* A; const bf16* Wh; const bf16* Wl;
            const float* bias; float* C; int rows; };
struct GBatch { GB g[6]; };

#define BK 32
#define KPAD 40
#define ARR_B   (128*KPAD*2)
#define STAGE_B (4*ARR_B)
#define DSMEM_B (2*STAGE_B)

__global__ __launch_bounds__(256, 2) void mma_gemm(GBatch batch) {
    const GB a = batch.g[blockIdx.z];
    const int brow = blockIdx.y * 128;
    if (brow >= a.rows) return;
    const int bcol = blockIdx.x * 128;

    extern __shared__ __align__(16) char dsm[];
    bf16* const sb = (bf16*)dsm;
    uint32_t smem_u32;
    {
        uint64_t t = __cvta_generic_to_shared(dsm);
        smem_u32 = (uint32_t)t;
    }

    const int tid = threadIdx.x;
    const int wid = tid >> 5, lane = tid & 31;
    const int warpM = wid & 3;
    const int warpN = wid >> 2;
    const int ra = lane >> 2;
    const int tk = (lane & 3) * 2;

    const int g8 = lane >> 3;
    const int r8 = lane & 7;
    const uint32_t a_ld_off = (uint32_t)((warpM*32 + (g8 & 1)*8 + r8) * KPAD
                                         + (g8 >> 1)*8) * 2;
    const uint32_t w_ld_off = (uint32_t)((warpN*64 + (g8 >> 1)*8 + r8) * KPAD
                                         + (g8 & 1)*8) * 2;

    const int ar = tid >> 1;
    const int ac = (tid & 1) * 4;
    const float* gA = a.A + (size_t)(brow + ar) * Dd + ac * 4;
    const int warr = tid >> 7;
    const int wr = tid & 127;
    const bf16* gW = (warr ? a.Wl : a.Wh) + (size_t)(bcol + wr) * Dd;
    const uint32_t wdst0 = smem_u32 + (2 + warr) * ARR_B + wr * (KPAD*2);

    float acc[2][8][4];
#pragma unroll
    for (int mi = 0; mi < 2; mi++)
#pragma unroll
        for (int ni = 0; ni < 8; ni++)
#pragma unroll
            for (int j = 0; j < 4; j++) acc[mi][ni][j] = 0.f;

    float4 pA[4];
#pragma unroll
    for (int i = 0; i < 4; i++) pA[i] = *(const float4*)(gA + i * 4);
#pragma unroll
    for (int q = 0; q < 4; q++)
        cp16(wdst0 + q * 16, gW + q * 8);
    cp_commit();

    for (int it = 0; it < 16; it++) {
        const int cur = it & 1;
        bf16* const Ah = sb + cur * (STAGE_B/2);
        bf16* const Al = Ah + ARR_B/2;
        const uint32_t stage = smem_u32 + cur * STAGE_B;

#pragma unroll
        for (int i = 0; i < 4; i++) {
            float4 v = pA[i];
            uint32_t h0, l0, h1, l1;
            split2(v.x, v.y, h0, l0);
            split2(v.z, v.w, h1, l1);
            *(uint2*)(Ah + ar*KPAD + (ac + i)*4) = make_uint2(h0, h1);
            *(uint2*)(Al + ar*KPAD + (ac + i)*4) = make_uint2(l0, l1);
        }

        if (it + 1 < 16) {
            const int k1 = (it + 1) * BK;
#pragma unroll
            for (int i = 0; i < 4; i++)
                pA[i] = *(const float4*)(gA + k1 + i * 4);
            const uint32_t wd = wdst0 + (cur ^ 1) * STAGE_B;
#pragma unroll
            for (int q = 0; q < 4; q++)
                cp16(wd + q * 16, gW + k1 + q * 8);
            cp_commit();
            cp_wait<1>();
        } else {
            cp_wait<0>();
        }
        __syncthreads();

#pragma unroll
        for (int ks = 0; ks < 2; ks++) {
            const uint32_t kso = ks * 32;
            uint32_t ah[2][4], al[2][4];
#pragma unroll
            for (int mi = 0; mi < 2; mi++) {
                const uint32_t ao = a_ld_off + mi * (16*KPAD*2) + kso;
                ldsm4(ah[mi], stage + ao);
                ldsm4(al[mi], stage + ARR_B + ao);
            }
#pragma unroll
            for (int np = 0; np < 4; np++) {
                uint32_t wh[4], wl[4];
                const uint32_t wo = w_ld_off + np * (16*KPAD*2) + kso;
                ldsm4(wh, stage + 2*ARR_B + wo);
                ldsm4(wl, stage + 3*ARR_B + wo);
#pragma unroll
                for (int mi = 0; mi < 2; mi++) {
                    float* c0 = acc[mi][2*np];
                    float* c1 = acc[mi][2*np + 1];
                    mma16816(c0, ah[mi][0], ah[mi][1], ah[mi][2], ah[mi][3], wh[0], wh[1]);
                    mma16816(c0, ah[mi][0], ah[mi][1], ah[mi][2], ah[mi][3], wl[0], wl[1]);
                    mma16816(c0, al[mi][0], al[mi][1], al[mi][2], al[mi][3], wh[0], wh[1]);
                    mma16816(c1, ah[mi][0], ah[mi][1], ah[mi][2], ah[mi][3], wh[2], wh[3]);
                    mma16816(c1, ah[mi][0], ah[mi][1], ah[mi][2], ah[mi][3], wl[2], wl[3]);
                    mma16816(c1, al[mi][0], al[mi][1], al[mi][2], al[mi][3], wh[2], wh[3]);
                }
            }
        }
        __syncthreads();
    }

#pragma unroll
    for (int mi = 0; mi < 2; mi++) {
        int row0 = brow + warpM * 32 + mi * 16 + ra;
#pragma unroll
        for (int ni = 0; ni < 8; ni++) {
            int col = bcol + warpN * 64 + ni * 8 + tk;
            float bx = a.bias[col], by = a.bias[col + 1];
            float2 o0 = make_float2(acc[mi][ni][0] + bx, acc[mi][ni][1] + by);
            float2 o1 = make_float2(acc[mi][ni][2] + bx, acc[mi][ni][3] + by);
            *(float2*)(a.C + (size_t)row0 * Dd + col) = o0;
            *(float2*)(a.C + (size_t)(row0 + 8) * Dd + col) = o1;
        }
    }
}

// ---------------------------------------------------------------------------
// FUSED attention kernel: blocks [0,1024) = static_pass1 chunks,
// blocks [1024, 1024+8192) = temporal (4 s-values per block).
// Both branches byte-identical logic to the proven separate kernels;
// shared memory overlaid in one dynamic buffer (29824 B).
// ---------------------------------------------------------------------------
#define QP 68
#define NSTATIC 1024
#define FUSED_SMEM_FLOATS 7456     // static: 7440, temporal: 6208
#define FUSED_SMEM_B (FUSED_SMEM_FLOATS*4)

__global__ __launch_bounds__(256, 4) void attn_fused(
    const float* __restrict__ Qt, const float* __restrict__ Kt,
    const float* __restrict__ Vt, const float* __restrict__ Qs,
    const float* __restrict__ Ksp, const float* __restrict__ Vsp,
    const int* __restrict__ mt, const int* __restrict__ ms,
    float* __restrict__ w_t, float* __restrict__ qkvt,
    float* __restrict__ w_s, float* __restrict__ smax,
    float* __restrict__ ssum, float* __restrict__ pout)
{
    extern __shared__ __align__(16) float sb[];
    const int tid = threadIdx.x;

    if (blockIdx.x < NSTATIC) {
        // ================= static_pass1 branch =================
        const int chunk = blockIdx.x & 15;
        const int bh = blockIdx.x >> 4;
        const int b = bh >> 3, h = bh & 7;

        float* sq = sb;                  // [16][68]
        float* sk = sb + 1088;           // [32][68]
        float* se = sb + 3264;           // [16][260]
        float* rowmax = sb + 7424;       // [16]

        {
            int qq = tid >> 4, c4 = tid & 15;
            float4 v = *(const float4*)(Qs + (size_t)(b*SSq + qq)*Dd + h*DH + c4*4);
            *(float4*)&sq[qq*68 + c4*4] = v;
        }
        __syncthreads();

        const int key0 = chunk * CH;
        for (int t = 0; t < 9; t++) {
            int cnt = min(32, CH - t*32);
            for (int i = tid; i < cnt*16; i += 256) {
                int kk = i >> 4, c4 = i & 15;
                int n = key0 + t*32 + kk;
                const float* kp = (n < SMf)
                    ? Kt + (size_t)(b*SMf + n)*Dd + h*DH
                    : Ksp + (size_t)(b*KSn + n - SMf)*Dd + h*DH;
                *(float4*)&sk[kk*68 + c4*4] = *(const float4*)(kp + c4*4);
            }
            __syncthreads();
            for (int p = tid; p < cnt*16; p += 256) {
                int qq = p & 15, kk = p >> 4;
                const float4* qp = (const float4*)&sq[qq*68];
                const float4* kp = (const float4*)&sk[kk*68];
                float acc = 0.f;
#pragma unroll
                for (int c = 0; c < 16; c++) {
                    float4 av = qp[c], bv = kp[c];
                    acc += av.x*bv.x + av.y*bv.y + av.z*bv.z + av.w*bv.w;
                }
                int n = key0 + t*32 + kk;
                int mv = (n < SMf) ? mt[b*SMf + n] : ms[b*KSn + n - SMf];
                se[qq*260 + t*32 + kk] = acc * SCALE + (mv ? 0.f : -1e30f);
            }
            __syncthreads();
        }

        const int q = tid >> 4, l = tid & 15;
        float lm = -1e38f;
        for (int j = l; j < CH; j += 16) lm = fmaxf(lm, se[q*260 + j]);
#pragma unroll
        for (int o = 8; o > 0; o >>= 1)
            lm = fmaxf(lm, __shfl_xor_sync(0xffffffffu, lm, o));
        if (l == 0) rowmax[q] = lm;
        __syncthreads();
        const float rm = rowmax[q];
        float ls = 0.f;
        const size_t wbase = ((size_t)bh*SSq + q) * (size_t)NKEY + key0;
        for (int j = l; j < CH; j += 16) {
            float e = __expf(se[q*260 + j] - rm);
            se[q*260 + j] = e;
            w_s[wbase + j] = e;
            ls += e;
        }
#pragma unroll
        for (int o = 8; o > 0; o >>= 1)
            ls += __shfl_xor_sync(0xffffffffu, ls, o);
        if (l == 0) {
            int si = (bh*16 + chunk)*16 + q;
            smax[si] = rm; ssum[si] = ls;
        }
        __syncthreads();

        const int grp = tid >> 6, d = tid & 63;
        float acc[16];
#pragma unroll
        for (int i = 0; i < 16; i++) acc[i] = 0.f;
        for (int j = grp; j < CH; j += 4) {
            int n = key0 + j;
            const float* vp = (n < SMf)
                ? Vt + (size_t)(b*SMf + n)*Dd + h*DH
                : Vsp + (size_t)(b*KSn + n - SMf)*Dd + h*DH;
            float vv = vp[d];
#pragma unroll
            for (int qq = 0; qq < 16; qq++) acc[qq] += se[qq*260 + j] * vv;
        }
        const size_t pb = ((size_t)((bh*16 + chunk)*4 + grp) * 16) * 64 + d;
#pragma unroll
        for (int qq = 0; qq < 16; qq++)
            pout[pb + (size_t)qq*64] = acc[qq];

    } else {
        // ================= temporal branch =================
        const int bx = blockIdx.x - NSTATIC;     // 0..8191
        const int g  = tid >> 6;
        const int d  = tid & 63;
        const int s4 = bx % (Ss_/4);
        const int h  = (bx / (Ss_/4)) % Hh;
        const int b  = bx / ((Ss_/4) * Hh);
        const int s  = s4 * 4 + g;

        float* q  = sb;                  // [4][8][68]
        float* k  = sb + 2176;           // [4][8][68]
        float* ks = sb + 4352;           // [16][68]
        float* sc = sb + 5440;           // [4][8][24]

        const size_t base_t = ((size_t)(b*Ss_ + s) * Mm) * Dd + (size_t)h * DH;
#pragma unroll
        for (int m = 0; m < Mm; m++) {
            q[(g*Mm + m)*QP + d] = Qt[base_t + (size_t)m*Dd + d];
            k[(g*Mm + m)*QP + d] = Kt[base_t + (size_t)m*Dd + d];
        }
        const size_t base_s = (size_t)b*KSn*Dd + (size_t)h*DH;
#pragma unroll
        for (int i = 0; i < 4; i++) {
            int n = g * 4 + i;
            ks[n*QP + d] = Ksp[base_s + (size_t)n*Dd + d];
        }
        __syncthreads();

        for (int e = d; e < Mm*(Mm+KSn); e += 64) {
            int m = e / (Mm+KSn), n = e % (Mm+KSn);
            const float4* kp = (const float4*)((n < Mm) ? &k[(g*Mm + n)*QP]
                                                        : &ks[(n-Mm)*QP]);
            const float4* qp = (const float4*)&q[(g*Mm + m)*QP];
            float acc = 0.f;
#pragma unroll
            for (int c = 0; c < DH/4; c++) {
                float4 av = qp[c], bv = kp[c];
                acc += av.x*bv.x + av.y*bv.y + av.z*bv.z + av.w*bv.w;
            }
            int maskv = (n < Mm) ? mt[(b*Ss_+s)*Mm + n] : ms[b*KSn + (n-Mm)];
            sc[(g*Mm + m)*24 + n] = acc * SCALE + (maskv ? 0.f : -1e30f);
        }
        __syncthreads();

        {
            const int m = d >> 3;
            const int l = d & 7;
            float* scr = &sc[(g*Mm + m)*24];
            float s0 = scr[l], s1 = scr[l+8], s2 = scr[l+16];
            float lm = fmaxf(s0, fmaxf(s1, s2));
#pragma unroll
            for (int o = 4; o > 0; o >>= 1)
                lm = fmaxf(lm, __shfl_xor_sync(0xffffffffu, lm, o, 8));
            float e0 = __expf(s0 - lm), e1 = __expf(s1 - lm), e2 = __expf(s2 - lm);
            float ls = e0 + e1 + e2;
#pragma unroll
            for (int o = 4; o > 0; o >>= 1)
                ls += __shfl_xor_sync(0xffffffffu, ls, o, 8);
            const float inv = 1.f / ls;
            e0 *= inv; e1 *= inv; e2 *= inv;
            scr[l] = e0; scr[l+8] = e1; scr[l+16] = e2;
            const size_t wb = ((((size_t)(b*Hh+h)*Ss_ + s) * Mm) + m) * (Mm+KSn);
            w_t[wb + l]      = e0;
            w_t[wb + l + 8]  = e1;
            w_t[wb + l + 16] = e2;
        }
        __syncthreads();

        {
            float accv[Mm];
#pragma unroll
            for (int m = 0; m < Mm; m++) accv[m] = 0.f;
#pragma unroll
            for (int n = 0; n < Mm; n++) {
                float vv = Vt[base_t + (size_t)n*Dd + d];
#pragma unroll
                for (int m = 0; m < Mm; m++)
                    accv[m] += sc[(g*Mm + m)*24 + n] * vv;
            }
#pragma unroll
            for (int n = 0; n < KSn; n++) {
                float vv = Vsp[base_s + (size_t)n*Dd + d];
#pragma unroll
                for (int m = 0; m < Mm; m++)
                    accv[m] += sc[(g*Mm + m)*24 + Mm + n] * vv;
            }
#pragma unroll
            for (int m = 0; m < Mm; m++)
                qkvt[base_t + (size_t)m*Dd + d] = accv[m];
        }
    }
}

// ---------------------------------------------------------------------------
// Static attention pass 2 (unchanged)
// ---------------------------------------------------------------------------
__global__ __launch_bounds__(128) void static_pass2(
    const float* __restrict__ smax, const float* __restrict__ ssum,
    const float* __restrict__ pout, float* __restrict__ w_s,
    float* __restrict__ qkvs)
{
    const int q = blockIdx.x & 15;
    const int bh = blockIdx.x >> 4;
    const int b = bh >> 3, h = bh & 7;
    const int tid = threadIdx.x;

    __shared__ float fac[16];

    float gmax = -1e38f;
#pragma unroll
    for (int c = 0; c < 16; c++)
        gmax = fmaxf(gmax, smax[(bh*16 + c)*16 + q]);
    float Z = 0.f;
#pragma unroll
    for (int c = 0; c < 16; c++)
        Z += ssum[(bh*16 + c)*16 + q] * __expf(smax[(bh*16 + c)*16 + q] - gmax);
    const float invZ = 1.f / Z;
    if (tid < 16)
        fac[tid] = __expf(smax[(bh*16 + tid)*16 + q] - gmax) * invZ;
    __syncthreads();

    if (tid < 64) {
        float o = 0.f;
#pragma unroll
        for (int c = 0; c < 16; c++) {
            float s4 = 0.f;
            size_t pb = ((size_t)((bh*16 + c)*4) * 16 + q) * 64 + tid;
#pragma unroll
            for (int g = 0; g < 4; g++) s4 += pout[pb + (size_t)g*16*64];
            o += fac[c] * s4;
        }
        qkvs[(size_t)(b*SSq + q)*Dd + h*DH + tid] = o;
    }

    const size_t wbase = ((size_t)bh*SSq + q) * (size_t)NKEY;
    for (int n = tid; n < NKEY; n += 128)
        w_s[wbase + n] *= fac[n / CH];
}

// ---------------------------------------------------------------------------
extern "C" void kernel_launch(void* const* d_in, const int* in_sizes, int n_in,
                              void* d_out, int out_size)
{
    (void)in_sizes; (void)n_in; (void)out_size;
    const float* q_t = (const float*)d_in[0];
    const float* k_t = (const float*)d_in[1];
    const float* v_t = (const float*)d_in[2];
    const float* q_s = (const float*)d_in[3];
    const float* k_s = (const float*)d_in[4];
    const float* v_s = (const float*)d_in[5];
    const int*   m_t = (const int*)d_in[6];
    const int*   m_s = (const int*)d_in[7];
    const float* Wq = (const float*)d_in[8];
    const float* bq = (const float*)d_in[9];
    const float* Wk = (const float*)d_in[10];
    const float* bk = (const float*)d_in[11];
    const float* Wv = (const float*)d_in[12];
    const float* bv = (const float*)d_in[13];
    const float* Wo = (const float*)d_in[14];
    const float* bo = (const float*)d_in[15];

    float* out   = (float*)d_out;
    float* out_t = out;
    float* w_t   = out_t + (size_t)Bb*Ss_*Mm*Dd;
    float* out_s = w_t + (size_t)Bb*Hh*Ss_*Mm*(Mm+KSn);
    float* w_s   = out_s + (size_t)Bb*SSq*Dd;

    float *p_qt, *p_kt, *p_vt, *p_qkvt, *p_qs, *p_ks, *p_vs, *p_qkvs;
    float *p_smax, *p_ssum, *p_pout;
    bf16 *p_wth, *p_wtl;
    cudaGetSymbolAddress((void**)&p_qt,   g_qt);
    cudaGetSymbolAddress((void**)&p_kt,   g_kt);
    cudaGetSymbolAddress((void**)&p_vt,   g_vt);
    cudaGetSymbolAddress((void**)&p_qkvt, g_qkvt);
    cudaGetSymbolAddress((void**)&p_qs,   g_qs);
    cudaGetSymbolAddress((void**)&p_ks,   g_ks);
    cudaGetSymbolAddress((void**)&p_vs,   g_vs);
    cudaGetSymbolAddress((void**)&p_qkvs, g_qkvs);
    cudaGetSymbolAddress((void**)&p_wth,  g_wth);
    cudaGetSymbolAddress((void**)&p_wtl,  g_wtl);
    cudaGetSymbolAddress((void**)&p_smax, g_smax);
    cudaGetSymbolAddress((void**)&p_ssum, g_ssum);
    cudaGetSymbolAddress((void**)&p_pout, g_pout);

    const size_t WSZ = (size_t)Dd * Dd;
    bf16* wqh = p_wth + 0*WSZ; bf16* wql = p_wtl + 0*WSZ;
    bf16* wkh = p_wth + 1*WSZ; bf16* wkl = p_wtl + 1*WSZ;
    bf16* wvh = p_wth + 2*WSZ; bf16* wvl = p_wtl + 2*WSZ;
    bf16* woh = p_wth + 3*WSZ; bf16* wol = p_wtl + 3*WSZ;

    cudaFuncSetAttribute(mma_gemm, cudaFuncAttributeMaxDynamicSharedMemorySize,
                         DSMEM_B);

    // 1) weight transpose+split
    WArgs wa;
    wa.W[0] = Wq; wa.Wh[0] = wqh; wa.Wl[0] = wql;
    wa.W[1] = Wk; wa.Wh[1] = wkh; wa.Wl[1] = wkl;
    wa.W[2] = Wv; wa.Wh[2] = wvh; wa.Wl[2] = wvl;
    wa.W[3] = Wo; wa.Wh[3] = woh; wa.Wl[3] = wol;
    wsplit_kernel<<<dim3(16,16,4), dim3(32,8)>>>(wa);

    // 2) all six input projections in one batched launch
    GBatch pb;
    pb.g[0] = { q_t, wqh, wql, bq, p_qt, TROWS };
    pb.g[1] = { k_t, wkh, wkl, bk, p_kt, TROWS };
    pb.g[2] = { v_t, wvh, wvl, bv, p_vt, TROWS };
    pb.g[3] = { q_s, wqh, wql, bq, p_qs, SROWS };
    pb.g[4] = { k_s, wkh, wkl, bk, p_ks, SROWS };
    pb.g[5] = { v_s, wvh, wvl, bv, p_vs, SROWS };
    mma_gemm<<<dim3(4, 256, 6), 256, DSMEM_B>>>(pb);

    // 3) fused attention (static chunks first, temporal fills behind)
    attn_fused<<<NSTATIC + Bb*Hh*(Ss_/4), 256, FUSED_SMEM_B>>>(
        p_qt, p_kt, p_vt, p_qs, p_ks, p_vs, m_t, m_s,
        w_t, p_qkvt, w_s, p_smax, p_ssum, p_pout);
    static_pass2<<<1024, 128>>>(p_smax, p_ssum, p_pout, w_s, p_qkvs);

    // 4) output projections (2 real GEMMs)
    GBatch ob;
    ob.g[0] = { p_qkvt, woh, wol, bo, out_t, TROWS };
    ob.g[1] = { p_qkvs, woh, wol, bo, out_s, SROWS };
    ob.g[2] = ob.g[1]; ob.g[3] = ob.g[1]; ob.g[4] = ob.g[1]; ob.g[5] = ob.g[1];
    mma_gemm<<<dim3(4, 256, 2), 256, DSMEM_B>>>(ob);
}

// round 16
// speedup vs baseline: 1.6286x; 1.6097x over previous
#include <cuda_runtime.h>
#include <cuda_fp16.h>
#include <cstdint>
#include <math.h>

// Problem constants
#define Bb 8
#define Ss_ 512
#define Mm 8
#define Dd 512
#define Hh 8
#define DH 64
#define SSq 16
#define KSn 16
#define SMf 4096
#define NKEY (SMf + KSn)
#define SCALE 0.125f
#define CH 257

#define TROWS (Bb*Ss_*Mm)  // 32768
#define SROWS (Bb*SSq)     // 128

// ---------------------------------------------------------------------------
// Scratch (device globals — no allocation allowed)
// ---------------------------------------------------------------------------
__device__ float g_qt[(size_t)TROWS*Dd];
__device__ float g_kt[(size_t)TROWS*Dd];
__device__ float g_vt[(size_t)TROWS*Dd];
__device__ float g_qkvt[(size_t)TROWS*Dd];
__device__ float g_qs[(size_t)SROWS*Dd];
__device__ float g_ks[(size_t)SROWS*Dd];
__device__ float g_vs[(size_t)SROWS*Dd];
__device__ float g_qkvs[(size_t)SROWS*Dd];
__device__ __half g_wt[4][(size_t)Dd*Dd];   // transposed fp16 weights
__device__ float g_smax[64*16*16];
__device__ float g_ssum[64*16*16];
__device__ float g_pout[(size_t)64*16*4*16*64];

// ---------------------------------------------------------------------------
__device__ __forceinline__ void mma16816_f16(float* c,
    uint32_t a0, uint32_t a1, uint32_t a2, uint32_t a3,
    uint32_t b0, uint32_t b1)
{
    asm volatile(
        "mma.sync.aligned.m16n8k16.row.col.f32.f16.f16.f32 "
        "{%0,%1,%2,%3}, {%4,%5,%6,%7}, {%8,%9}, {%0,%1,%2,%3};"
        : "+f"(c[0]), "+f"(c[1]), "+f"(c[2]), "+f"(c[3])
        : "r"(a0), "r"(a1), "r"(a2), "r"(a3), "r"(b0), "r"(b1));
}

__device__ __forceinline__ void ldsm4(uint32_t* r, uint32_t addr) {
    asm volatile(
        "ldmatrix.sync.aligned.m8n8.x4.shared.b16 {%0,%1,%2,%3}, [%4];"
        : "=r"(r[0]), "=r"(r[1]), "=r"(r[2]), "=r"(r[3]) : "r"(addr));
}

__device__ __forceinline__ void cp16(uint32_t smem_dst, const void* gsrc) {
    asm volatile("cp.async.cg.shared.global [%0], [%1], 16;"
                 :: "r"(smem_dst), "l"(gsrc));
}
__device__ __forceinline__ void cp_commit() {
    asm volatile("cp.async.commit_group;" ::: "memory");
}
template<int N>
__device__ __forceinline__ void cp_wait() {
    asm volatile("cp.async.wait_group %0;" :: "n"(N) : "memory");
}

__device__ __forceinline__ uint32_t h2u(__half2 v) {
    return *reinterpret_cast<uint32_t*>(&v);
}

// ---------------------------------------------------------------------------
// Weight transpose + convert to fp16: WT[n][k] = (half)W[k][n]
// ---------------------------------------------------------------------------
struct WArgs { const float* W[4]; __half* Wt[4]; };

__global__ __launch_bounds__(256) void wsplit_kernel(WArgs a) {
    const int z = blockIdx.z;
    const float* W = a.W[z];
    __half* Wt = a.Wt[z];
    __shared__ float t[32][33];
    const int x0 = blockIdx.x * 32, y0 = blockIdx.y * 32;
    const int tx = threadIdx.x, ty = threadIdx.y;
#pragma unroll
    for (int i = ty; i < 32; i += 8)
        t[i][tx] = W[(size_t)(y0 + i) * Dd + x0 + tx];
    __syncthreads();
#pragma unroll
    for (int i = ty; i < 32; i += 8) {
        float v = t[tx][i];
        Wt[(size_t)(x0 + i) * Dd + y0 + tx] = __float2half_rn(v);
    }
}

// ---------------------------------------------------------------------------
// MMA GEMM, single-term fp16: C = A(fp16) @ W(fp16)^T + bias, fp32 acc.
// Same skeleton as the proven bf16-3-term kernel: cp.async double-buffered W,
// register-prefetch + convert A, ldmatrix fragments. 32 MMA / iter.
// ---------------------------------------------------------------------------
struct GB { const float* A; const __half* Wt;
            const float* bias; float* C; int rows; };
struct GBatch { GB g[6]; };

#define BK 32
#define KPAD 40
#define ARR2_B   (128*KPAD*2)      // 10240 bytes per array
#define STAGE2_B (2*ARR2_B)        // 20480 (A | W)
#define DSMEM2_B (2*STAGE2_B)      // 40960

__global__ __launch_bounds__(256, 2) void mma_gemm(GBatch batch) {
    const GB a = batch.g[blockIdx.z];
    const int brow = blockIdx.y * 128;
    if (brow >= a.rows) return;
    const int bcol = blockIdx.x * 128;

    extern __shared__ __align__(16) char dsm[];
    __half* const sb = (__half*)dsm;
    uint32_t smem_u32;
    {
        uint64_t t = __cvta_generic_to_shared(dsm);
        smem_u32 = (uint32_t)t;
    }

    const int tid = threadIdx.x;
    const int wid = tid >> 5, lane = tid & 31;
    const int warpM = wid & 3;
    const int warpN = wid >> 2;
    const int ra = lane >> 2;
    const int tk = (lane & 3) * 2;

    const int g8 = lane >> 3;
    const int r8 = lane & 7;
    const uint32_t a_ld_off = (uint32_t)((warpM*32 + (g8 & 1)*8 + r8) * KPAD
                                         + (g8 >> 1)*8) * 2;
    const uint32_t w_ld_off = (uint32_t)((warpN*64 + (g8 >> 1)*8 + r8) * KPAD
                                         + (g8 & 1)*8) * 2;

    // A staging: 2 threads/row, 16 floats each (4 float4) -> 16 fp16
    const int ar = tid >> 1;
    const int ah4 = (tid & 1);               // half-of-row selector
    const float* gA = a.A + (size_t)(brow + ar) * Dd + ah4 * 16;
    // W staging via cp.async: 2 threads/row, 16 fp16 (32 B) each
    const int wr = tid >> 1;
    const int wc = (tid & 1);
    const __half* gW = a.Wt + (size_t)(bcol + wr) * Dd + wc * 16;
    const uint32_t wdst0 = smem_u32 + ARR2_B + wr * (KPAD*2) + wc * 32;

    float acc[2][8][4];
#pragma unroll
    for (int mi = 0; mi < 2; mi++)
#pragma unroll
        for (int ni = 0; ni < 8; ni++)
#pragma unroll
            for (int j = 0; j < 4; j++) acc[mi][ni][j] = 0.f;

    float4 pA[4];
#pragma unroll
    for (int i = 0; i < 4; i++) pA[i] = *(const float4*)(gA + i * 4);
    cp16(wdst0, gW);
    cp16(wdst0 + 16, gW + 8);
    cp_commit();

    for (int it = 0; it < 16; it++) {
        const int cur = it & 1;
        __half* const Ad = sb + cur * (STAGE2_B/2);
        const uint32_t stage = smem_u32 + cur * STAGE2_B;

        // ---- store A tile (fp32 -> fp16) ----
        {
            __half* dst = Ad + ar*KPAD + ah4*16;
#pragma unroll
            for (int i = 0; i < 2; i++) {
                float4 v0 = pA[2*i], v1 = pA[2*i+1];
                uint4 o;
                o.x = h2u(__floats2half2_rn(v0.x, v0.y));
                o.y = h2u(__floats2half2_rn(v0.z, v0.w));
                o.z = h2u(__floats2half2_rn(v1.x, v1.y));
                o.w = h2u(__floats2half2_rn(v1.z, v1.w));
                *(uint4*)(dst + i*8) = o;
            }
        }

        if (it + 1 < 16) {
            const int k1 = (it + 1) * BK;
#pragma unroll
            for (int i = 0; i < 4; i++)
                pA[i] = *(const float4*)(gA + k1 + i * 4);
            const uint32_t wd = wdst0 + (cur ^ 1) * STAGE2_B;
            cp16(wd, gW + k1);
            cp16(wd + 16, gW + k1 + 8);
            cp_commit();
            cp_wait<1>();
        } else {
            cp_wait<0>();
        }
        __syncthreads();

        // ---- compute: 2 k16 steps, 16 MMA each ----
#pragma unroll
        for (int ks = 0; ks < 2; ks++) {
            const uint32_t kso = ks * 32;
            uint32_t ah[2][4];
#pragma unroll
            for (int mi = 0; mi < 2; mi++)
                ldsm4(ah[mi], stage + a_ld_off + mi * (16*KPAD*2) + kso);
#pragma unroll
            for (int np = 0; np < 4; np++) {
                uint32_t wf[4];
                ldsm4(wf, stage + ARR2_B + w_ld_off + np * (16*KPAD*2) + kso);
#pragma unroll
                for (int mi = 0; mi < 2; mi++) {
                    mma16816_f16(acc[mi][2*np],
                                 ah[mi][0], ah[mi][1], ah[mi][2], ah[mi][3],
                                 wf[0], wf[1]);
                    mma16816_f16(acc[mi][2*np + 1],
                                 ah[mi][0], ah[mi][1], ah[mi][2], ah[mi][3],
                                 wf[2], wf[3]);
                }
            }
        }
        __syncthreads();
    }

#pragma unroll
    for (int mi = 0; mi < 2; mi++) {
        int row0 = brow + warpM * 32 + mi * 16 + ra;
#pragma unroll
        for (int ni = 0; ni < 8; ni++) {
            int col = bcol + warpN * 64 + ni * 8 + tk;
            float bx = a.bias[col], by = a.bias[col + 1];
            float2 o0 = make_float2(acc[mi][ni][0] + bx, acc[mi][ni][1] + by);
            float2 o1 = make_float2(acc[mi][ni][2] + bx, acc[mi][ni][3] + by);
            *(float2*)(a.C + (size_t)row0 * Dd + col) = o0;
            *(float2*)(a.C + (size_t)(row0 + 8) * Dd + col) = o1;
        }
    }
}

// ---------------------------------------------------------------------------
// FUSED attention kernel (round-15, unchanged — measured best)
// ---------------------------------------------------------------------------
#define QP 68
#define NSTATIC 1024
#define FUSED_SMEM_FLOATS 7456
#define FUSED_SMEM_B (FUSED_SMEM_FLOATS*4)

__global__ __launch_bounds__(256, 4) void attn_fused(
    const float* __restrict__ Qt, const float* __restrict__ Kt,
    const float* __restrict__ Vt, const float* __restrict__ Qs,
    const float* __restrict__ Ksp, const float* __restrict__ Vsp,
    const int* __restrict__ mt, const int* __restrict__ ms,
    float* __restrict__ w_t, float* __restrict__ qkvt,
    float* __restrict__ w_s, float* __restrict__ smax,
    float* __restrict__ ssum, float* __restrict__ pout)
{
    extern __shared__ __align__(16) float sb[];
    const int tid = threadIdx.x;

    if (blockIdx.x < NSTATIC) {
        const int chunk = blockIdx.x & 15;
        const int bh = blockIdx.x >> 4;
        const int b = bh >> 3, h = bh & 7;

        float* sq = sb;
        float* sk = sb + 1088;
        float* se = sb + 3264;
        float* rowmax = sb + 7424;

        {
            int qq = tid >> 4, c4 = tid & 15;
            float4 v = *(const float4*)(Qs + (size_t)(b*SSq + qq)*Dd + h*DH + c4*4);
            *(float4*)&sq[qq*68 + c4*4] = v;
        }
        __syncthreads();

        const int key0 = chunk * CH;
        for (int t = 0; t < 9; t++) {
            int cnt = min(32, CH - t*32);
            for (int i = tid; i < cnt*16; i += 256) {
                int kk = i >> 4, c4 = i & 15;
                int n = key0 + t*32 + kk;
                const float* kp = (n < SMf)
                    ? Kt + (size_t)(b*SMf + n)*Dd + h*DH
                    : Ksp + (size_t)(b*KSn + n - SMf)*Dd + h*DH;
                *(float4*)&sk[kk*68 + c4*4] = *(const float4*)(kp + c4*4);
            }
            __syncthreads();
            for (int p = tid; p < cnt*16; p += 256) {
                int qq = p & 15, kk = p >> 4;
                const float4* qp = (const float4*)&sq[qq*68];
                const float4* kp = (const float4*)&sk[kk*68];
                float acc = 0.f;
#pragma unroll
                for (int c = 0; c < 16; c++) {
                    float4 av = qp[c], bv = kp[c];
                    acc += av.x*bv.x + av.y*bv.y + av.z*bv.z + av.w*bv.w;
                }
                int n = key0 + t*32 + kk;
                int mv = (n < SMf) ? mt[b*SMf + n] : ms[b*KSn + n - SMf];
                se[qq*260 + t*32 + kk] = acc * SCALE + (mv ? 0.f : -1e30f);
            }
            __syncthreads();
        }

        const int q = tid >> 4, l = tid & 15;
        float lm = -1e38f;
        for (int j = l; j < CH; j += 16) lm = fmaxf(lm, se[q*260 + j]);
#pragma unroll
        for (int o = 8; o > 0; o >>= 1)
            lm = fmaxf(lm, __shfl_xor_sync(0xffffffffu, lm, o));
        if (l == 0) rowmax[q] = lm;
        __syncthreads();
        const float rm = rowmax[q];
        float ls = 0.f;
        const size_t wbase = ((size_t)bh*SSq + q) * (size_t)NKEY + key0;
        for (int j = l; j < CH; j += 16) {
            float e = __expf(se[q*260 + j] - rm);
            se[q*260 + j] = e;
            w_s[wbase + j] = e;
            ls += e;
        }
#pragma unroll
        for (int o = 8; o > 0; o >>= 1)
            ls += __shfl_xor_sync(0xffffffffu, ls, o);
        if (l == 0) {
            int si = (bh*16 + chunk)*16 + q;
            smax[si] = rm; ssum[si] = ls;
        }
        __syncthreads();

        const int grp = tid >> 6, d = tid & 63;
        float acc[16];
#pragma unroll
        for (int i = 0; i < 16; i++) acc[i] = 0.f;
        for (int j = grp; j < CH; j += 4) {
            int n = key0 + j;
            const float* vp = (n < SMf)
                ? Vt + (size_t)(b*SMf + n)*Dd + h*DH
                : Vsp + (size_t)(b*KSn + n - SMf)*Dd + h*DH;
            float vv = vp[d];
#pragma unroll
            for (int qq = 0; qq < 16; qq++) acc[qq] += se[qq*260 + j] * vv;
        }
        const size_t pb = ((size_t)((bh*16 + chunk)*4 + grp) * 16) * 64 + d;
#pragma unroll
        for (int qq = 0; qq < 16; qq++)
            pout[pb + (size_t)qq*64] = acc[qq];

    } else {
        const int bx = blockIdx.x - NSTATIC;
        const int g  = tid >> 6;
        const int d  = tid & 63;
        const int s4 = bx % (Ss_/4);
        const int h  = (bx / (Ss_/4)) % Hh;
        const int b  = bx / ((Ss_/4) * Hh);
        const int s  = s4 * 4 + g;

        float* q  = sb;
        float* k  = sb + 2176;
        float* ks = sb + 4352;
        float* sc = sb + 5440;

        const size_t base_t = ((size_t)(b*Ss_ + s) * Mm) * Dd + (size_t)h * DH;
#pragma unroll
        for (int m = 0; m < Mm; m++) {
            q[(g*Mm + m)*QP + d] = Qt[base_t + (size_t)m*Dd + d];
            k[(g*Mm + m)*QP + d] = Kt[base_t + (size_t)m*Dd + d];
        }
        const size_t base_s = (size_t)b*KSn*Dd + (size_t)h*DH;
#pragma unroll
        for (int i = 0; i < 4; i++) {
            int n = g * 4 + i;
            ks[n*QP + d] = Ksp[base_s + (size_t)n*Dd + d];
        }
        __syncthreads();

        for (int e = d; e < Mm*(Mm+KSn); e += 64) {
            int m = e / (Mm+KSn), n = e % (Mm+KSn);
            const float4* kp = (const float4*)((n < Mm) ? &k[(g*Mm + n)*QP]
                                                        : &ks[(n-Mm)*QP]);
            const float4* qp = (const float4*)&q[(g*Mm + m)*QP];
            float acc = 0.f;
#pragma unroll
            for (int c = 0; c < DH/4; c++) {
                float4 av = qp[c], bv = kp[c];
                acc += av.x*bv.x + av.y*bv.y + av.z*bv.z + av.w*bv.w;
            }
            int maskv = (n < Mm) ? mt[(b*Ss_+s)*Mm + n] : ms[b*KSn + (n-Mm)];
            sc[(g*Mm + m)*24 + n] = acc * SCALE + (maskv ? 0.f : -1e30f);
        }
        __syncthreads();

        {
            const int m = d >> 3;
            const int l = d & 7;
            float* scr = &sc[(g*Mm + m)*24];
            float s0 = scr[l], s1 = scr[l+8], s2 = scr[l+16];
            float lm = fmaxf(s0, fmaxf(s1, s2));
#pragma unroll
            for (int o = 4; o > 0; o >>= 1)
                lm = fmaxf(lm, __shfl_xor_sync(0xffffffffu, lm, o, 8));
            float e0 = __expf(s0 - lm), e1 = __expf(s1 - lm), e2 = __expf(s2 - lm);
            float ls = e0 + e1 + e2;
#pragma unroll
            for (int o = 4; o > 0; o >>= 1)
                ls += __shfl_xor_sync(0xffffffffu, ls, o, 8);
            const float inv = 1.f / ls;
            e0 *= inv; e1 *= inv; e2 *= inv;
            scr[l] = e0; scr[l+8] = e1; scr[l+16] = e2;
            const size_t wb = ((((size_t)(b*Hh+h)*Ss_ + s) * Mm) + m) * (Mm+KSn);
            w_t[wb + l]      = e0;
            w_t[wb + l + 8]  = e1;
            w_t[wb + l + 16] = e2;
        }
        __syncthreads();

        {
            float accv[Mm];
#pragma unroll
            for (int m = 0; m < Mm; m++) accv[m] = 0.f;
#pragma unroll
            for (int n = 0; n < Mm; n++) {
                float vv = Vt[base_t + (size_t)n*Dd + d];
#pragma unroll
                for (int m = 0; m < Mm; m++)
                    accv[m] += sc[(g*Mm + m)*24 + n] * vv;
            }
#pragma unroll
            for (int n = 0; n < KSn; n++) {
                float vv = Vsp[base_s + (size_t)n*Dd + d];
#pragma unroll
                for (int m = 0; m < Mm; m++)
                    accv[m] += sc[(g*Mm + m)*24 + Mm + n] * vv;
            }
#pragma unroll
            for (int m = 0; m < Mm; m++)
                qkvt[base_t + (size_t)m*Dd + d] = accv[m];
        }
    }
}

// ---------------------------------------------------------------------------
// Static attention pass 2 (unchanged)
// ---------------------------------------------------------------------------
__global__ __launch_bounds__(128) void static_pass2(
    const float* __restrict__ smax, const float* __restrict__ ssum,
    const float* __restrict__ pout, float* __restrict__ w_s,
    float* __restrict__ qkvs)
{
    const int q = blockIdx.x & 15;
    const int bh = blockIdx.x >> 4;
    const int b = bh >> 3, h = bh & 7;
    const int tid = threadIdx.x;

    __shared__ float fac[16];

    float gmax = -1e38f;
#pragma unroll
    for (int c = 0; c < 16; c++)
        gmax = fmaxf(gmax, smax[(bh*16 + c)*16 + q]);
    float Z = 0.f;
#pragma unroll
    for (int c = 0; c < 16; c++)
        Z += ssum[(bh*16 + c)*16 + q] * __expf(smax[(bh*16 + c)*16 + q] - gmax);
    const float invZ = 1.f / Z;
    if (tid < 16)
        fac[tid] = __expf(smax[(bh*16 + tid)*16 + q] - gmax) * invZ;
    __syncthreads();

    if (tid < 64) {
        float o = 0.f;
#pragma unroll
        for (int c = 0; c < 16; c++) {
            float s4 = 0.f;
            size_t pb = ((size_t)((bh*16 + c)*4) * 16 + q) * 64 + tid;
#pragma unroll
            for (int g = 0; g < 4; g++) s4 += pout[pb + (size_t)g*16*64];
            o += fac[c] * s4;
        }
        qkvs[(size_t)(b*SSq + q)*Dd + h*DH + tid] = o;
    }

    const size_t wbase = ((size_t)bh*SSq + q) * (size_t)NKEY;
    for (int n = tid; n < NKEY; n += 128)
        w_s[wbase + n] *= fac[n / CH];
}

// ---------------------------------------------------------------------------
extern "C" void kernel_launch(void* const* d_in, const int* in_sizes, int n_in,
                              void* d_out, int out_size)
{
    (void)in_sizes; (void)n_in; (void)out_size;
    const float* q_t = (const float*)d_in[0];
    const float* k_t = (const float*)d_in[1];
    const float* v_t = (const float*)d_in[2];
    const float* q_s = (const float*)d_in[3];
    const float* k_s = (const float*)d_in[4];
    const float* v_s = (const float*)d_in[5];
    const int*   m_t = (const int*)d_in[6];
    const int*   m_s = (const int*)d_in[7];
    const float* Wq = (const float*)d_in[8];
    const float* bq = (const float*)d_in[9];
    const float* Wk = (const float*)d_in[10];
    const float* bk = (const float*)d_in[11];
    const float* Wv = (const float*)d_in[12];
    const float* bv = (const float*)d_in[13];
    const float* Wo = (const float*)d_in[14];
    const float* bo = (const float*)d_in[15];

    float* out   = (float*)d_out;
    float* out_t = out;
    float* w_t   = out_t + (size_t)Bb*Ss_*Mm*Dd;
    float* out_s = w_t + (size_t)Bb*Hh*Ss_*Mm*(Mm+KSn);
    float* w_s   = out_s + (size_t)Bb*SSq*Dd;

    float *p_qt, *p_kt, *p_vt, *p_qkvt, *p_qs, *p_ks, *p_vs, *p_qkvs;
    float *p_smax, *p_ssum, *p_pout;
    __half *p_wt;
    cudaGetSymbolAddress((void**)&p_qt,   g_qt);
    cudaGetSymbolAddress((void**)&p_kt,   g_kt);
    cudaGetSymbolAddress((void**)&p_vt,   g_vt);
    cudaGetSymbolAddress((void**)&p_qkvt, g_qkvt);
    cudaGetSymbolAddress((void**)&p_qs,   g_qs);
    cudaGetSymbolAddress((void**)&p_ks,   g_ks);
    cudaGetSymbolAddress((void**)&p_vs,   g_vs);
    cudaGetSymbolAddress((void**)&p_qkvs, g_qkvs);
    cudaGetSymbolAddress((void**)&p_wt,   g_wt);
    cudaGetSymbolAddress((void**)&p_smax, g_smax);
    cudaGetSymbolAddress((void**)&p_ssum, g_ssum);
    cudaGetSymbolAddress((void**)&p_pout, g_pout);

    const size_t WSZ = (size_t)Dd * Dd;
    __half* wq = p_wt + 0*WSZ;
    __half* wk = p_wt + 1*WSZ;
    __half* wv = p_wt + 2*WSZ;
    __half* wo = p_wt + 3*WSZ;

    cudaFuncSetAttribute(mma_gemm, cudaFuncAttributeMaxDynamicSharedMemorySize,
                         DSMEM2_B);

    // 1) weight transpose + fp16 convert
    WArgs wa;
    wa.W[0] = Wq; wa.Wt[0] = wq;
    wa.W[1] = Wk; wa.Wt[1] = wk;
    wa.W[2] = Wv; wa.Wt[2] = wv;
    wa.W[3] = Wo; wa.Wt[3] = wo;
    wsplit_kernel<<<dim3(16,16,4), dim3(32,8)>>>(wa);

    // 2) all six input projections in one batched launch
    GBatch pb;
    pb.g[0] = { q_t, wq, bq, p_qt, TROWS };
    pb.g[1] = { k_t, wk, bk, p_kt, TROWS };
    pb.g[2] = { v_t, wv, bv, p_vt, TROWS };
    pb.g[3] = { q_s, wq, bq, p_qs, SROWS };
    pb.g[4] = { k_s, wk, bk, p_ks, SROWS };
    pb.g[5] = { v_s, wv, bv, p_vs, SROWS };
    mma_gemm<<<dim3(4, 256, 6), 256, DSMEM2_B>>>(pb);

    // 3) fused attention + combine
    attn_fused<<<NSTATIC + Bb*Hh*(Ss_/4), 256, FUSED_SMEM_B>>>(
        p_qt, p_kt, p_vt, p_qs, p_ks, p_vs, m_t, m_s,
        w_t, p_qkvt, w_s, p_smax, p_ssum, p_pout);
    static_pass2<<<1024, 128>>>(p_smax, p_ssum, p_pout, w_s, p_qkvs);

    // 4) output projections (2 real GEMMs)
    GBatch ob;
    ob.g[0] = { p_qkvt, wo, bo, out_t, TROWS };
    ob.g[1] = { p_qkvs, wo, bo, out_s, SROWS };
    ob.g[2] = ob.g[1]; ob.g[3] = ob.g[1]; ob.g[4] = ob.g[1]; ob.g[5] = ob.g[1];
    mma_gemm<<<dim3(4, 256, 2), 256, DSMEM2_B>>>(ob);
}

// round 17
// speedup vs baseline: 1.6704x; 1.0256x over previous
#include <cuda_runtime.h>
#include <cuda_fp16.h>
#include <cstdint>
#include <math.h>

// Problem constants
#define Bb 8
#define Ss_ 512
#define Mm 8
#define Dd 512
#define Hh 8
#define DH 64
#define SSq 16
#define KSn 16
#define SMf 4096
#define NKEY (SMf + KSn)
#define SCALE 0.125f
#define NCHUNK 32
#define CH 129             // 31*129 + 113 = 4112

#define TROWS (Bb*Ss_*Mm)  // 32768
#define SROWS (Bb*SSq)     // 128

// ---------------------------------------------------------------------------
// Scratch (device globals — no allocation allowed)
// ---------------------------------------------------------------------------
__device__ float g_qt[(size_t)TROWS*Dd];
__device__ float g_kt[(size_t)TROWS*Dd];
__device__ float g_vt[(size_t)TROWS*Dd];
__device__ float g_qkvt[(size_t)TROWS*Dd];
__device__ float g_qs[(size_t)SROWS*Dd];
__device__ float g_ks[(size_t)SROWS*Dd];
__device__ float g_vs[(size_t)SROWS*Dd];
__device__ float g_qkvs[(size_t)SROWS*Dd];
__device__ __half g_wt[4][(size_t)Dd*Dd];
__device__ float g_smax[64*NCHUNK*16];
__device__ float g_ssum[64*NCHUNK*16];
__device__ float g_pout[(size_t)64*NCHUNK*4*16*64];

// ---------------------------------------------------------------------------
__device__ __forceinline__ void mma16816_f16(float* c,
    uint32_t a0, uint32_t a1, uint32_t a2, uint32_t a3,
    uint32_t b0, uint32_t b1)
{
    asm volatile(
        "mma.sync.aligned.m16n8k16.row.col.f32.f16.f16.f32 "
        "{%0,%1,%2,%3}, {%4,%5,%6,%7}, {%8,%9}, {%0,%1,%2,%3};"
        : "+f"(c[0]), "+f"(c[1]), "+f"(c[2]), "+f"(c[3])
        : "r"(a0), "r"(a1), "r"(a2), "r"(a3), "r"(b0), "r"(b1));
}

__device__ __forceinline__ void ldsm4(uint32_t* r, uint32_t addr) {
    asm volatile(
        "ldmatrix.sync.aligned.m8n8.x4.shared.b16 {%0,%1,%2,%3}, [%4];"
        : "=r"(r[0]), "=r"(r[1]), "=r"(r[2]), "=r"(r[3]) : "r"(addr));
}

__device__ __forceinline__ void cp16(uint32_t smem_dst, const void* gsrc) {
    asm volatile("cp.async.cg.shared.global [%0], [%1], 16;"
                 :: "r"(smem_dst), "l"(gsrc));
}
__device__ __forceinline__ void cp_commit() {
    asm volatile("cp.async.commit_group;" ::: "memory");
}
template<int N>
__device__ __forceinline__ void cp_wait() {
    asm volatile("cp.async.wait_group %0;" :: "n"(N) : "memory");
}

__device__ __forceinline__ uint32_t h2u(__half2 v) {
    return *reinterpret_cast<uint32_t*>(&v);
}

// ---------------------------------------------------------------------------
// Weight transpose + convert to fp16
// ---------------------------------------------------------------------------
struct WArgs { const float* W[4]; __half* Wt[4]; };

__global__ __launch_bounds__(256) void wsplit_kernel(WArgs a) {
    const int z = blockIdx.z;
    const float* W = a.W[z];
    __half* Wt = a.Wt[z];
    __shared__ float t[32][33];
    const int x0 = blockIdx.x * 32, y0 = blockIdx.y * 32;
    const int tx = threadIdx.x, ty = threadIdx.y;
#pragma unroll
    for (int i = ty; i < 32; i += 8)
        t[i][tx] = W[(size_t)(y0 + i) * Dd + x0 + tx];
    __syncthreads();
#pragma unroll
    for (int i = ty; i < 32; i += 8) {
        float v = t[tx][i];
        Wt[(size_t)(x0 + i) * Dd + y0 + tx] = __float2half_rn(v);
    }
}

// ---------------------------------------------------------------------------
// MMA GEMM, single-term fp16 (round-16 — measured best; unchanged)
// ---------------------------------------------------------------------------
struct GB { const float* A; const __half* Wt;
            const float* bias; float* C; int rows; };
struct GBatch { GB g[6]; };

#define BK 32
#define KPAD 40
#define ARR2_B   (128*KPAD*2)
#define STAGE2_B (2*ARR2_B)
#define DSMEM2_B (2*STAGE2_B)

__global__ __launch_bounds__(256, 2) void mma_gemm(GBatch batch) {
    const GB a = batch.g[blockIdx.z];
    const int brow = blockIdx.y * 128;
    if (brow >= a.rows) return;
    const int bcol = blockIdx.x * 128;

    extern __shared__ __align__(16) char dsm[];
    __half* const sb = (__half*)dsm;
    uint32_t smem_u32;
    {
        uint64_t t = __cvta_generic_to_shared(dsm);
        smem_u32 = (uint32_t)t;
    }

    const int tid = threadIdx.x;
    const int wid = tid >> 5, lane = tid & 31;
    const int warpM = wid & 3;
    const int warpN = wid >> 2;
    const int ra = lane >> 2;
    const int tk = (lane & 3) * 2;

    const int g8 = lane >> 3;
    const int r8 = lane & 7;
    const uint32_t a_ld_off = (uint32_t)((warpM*32 + (g8 & 1)*8 + r8) * KPAD
                                         + (g8 >> 1)*8) * 2;
    const uint32_t w_ld_off = (uint32_t)((warpN*64 + (g8 >> 1)*8 + r8) * KPAD
                                         + (g8 & 1)*8) * 2;

    const int ar = tid >> 1;
    const int ah4 = (tid & 1);
    const float* gA = a.A + (size_t)(brow + ar) * Dd + ah4 * 16;
    const int wr = tid >> 1;
    const int wc = (tid & 1);
    const __half* gW = a.Wt + (size_t)(bcol + wr) * Dd + wc * 16;
    const uint32_t wdst0 = smem_u32 + ARR2_B + wr * (KPAD*2) + wc * 32;

    float acc[2][8][4];
#pragma unroll
    for (int mi = 0; mi < 2; mi++)
#pragma unroll
        for (int ni = 0; ni < 8; ni++)
#pragma unroll
            for (int j = 0; j < 4; j++) acc[mi][ni][j] = 0.f;

    float4 pA[4];
#pragma unroll
    for (int i = 0; i < 4; i++) pA[i] = *(const float4*)(gA + i * 4);
    cp16(wdst0, gW);
    cp16(wdst0 + 16, gW + 8);
    cp_commit();

    for (int it = 0; it < 16; it++) {
        const int cur = it & 1;
        __half* const Ad = sb + cur * (STAGE2_B/2);
        const uint32_t stage = smem_u32 + cur * STAGE2_B;

        {
            __half* dst = Ad + ar*KPAD + ah4*16;
#pragma unroll
            for (int i = 0; i < 2; i++) {
                float4 v0 = pA[2*i], v1 = pA[2*i+1];
                uint4 o;
                o.x = h2u(__floats2half2_rn(v0.x, v0.y));
                o.y = h2u(__floats2half2_rn(v0.z, v0.w));
                o.z = h2u(__floats2half2_rn(v1.x, v1.y));
                o.w = h2u(__floats2half2_rn(v1.z, v1.w));
                *(uint4*)(dst + i*8) = o;
            }
        }

        if (it + 1 < 16) {
            const int k1 = (it + 1) * BK;
#pragma unroll
            for (int i = 0; i < 4; i++)
                pA[i] = *(const float4*)(gA + k1 + i * 4);
            const uint32_t wd = wdst0 + (cur ^ 1) * STAGE2_B;
            cp16(wd, gW + k1);
            cp16(wd + 16, gW + k1 + 8);
            cp_commit();
            cp_wait<1>();
        } else {
            cp_wait<0>();
        }
        __syncthreads();

#pragma unroll
        for (int ks = 0; ks < 2; ks++) {
            const uint32_t kso = ks * 32;
            uint32_t ah[2][4];
#pragma unroll
            for (int mi = 0; mi < 2; mi++)
                ldsm4(ah[mi], stage + a_ld_off + mi * (16*KPAD*2) + kso);
#pragma unroll
            for (int np = 0; np < 4; np++) {
                uint32_t wf[4];
                ldsm4(wf, stage + ARR2_B + w_ld_off + np * (16*KPAD*2) + kso);
#pragma unroll
                for (int mi = 0; mi < 2; mi++) {
                    mma16816_f16(acc[mi][2*np],
                                 ah[mi][0], ah[mi][1], ah[mi][2], ah[mi][3],
                                 wf[0], wf[1]);
                    mma16816_f16(acc[mi][2*np + 1],
                                 ah[mi][0], ah[mi][1], ah[mi][2], ah[mi][3],
                                 wf[2], wf[3]);
                }
            }
        }
        __syncthreads();
    }

#pragma unroll
    for (int mi = 0; mi < 2; mi++) {
        int row0 = brow + warpM * 32 + mi * 16 + ra;
#pragma unroll
        for (int ni = 0; ni < 8; ni++) {
            int col = bcol + warpN * 64 + ni * 8 + tk;
            float bx = a.bias[col], by = a.bias[col + 1];
            float2 o0 = make_float2(acc[mi][ni][0] + bx, acc[mi][ni][1] + by);
            float2 o1 = make_float2(acc[mi][ni][2] + bx, acc[mi][ni][3] + by);
            *(float2*)(a.C + (size_t)row0 * Dd + col) = o0;
            *(float2*)(a.C + (size_t)(row0 + 8) * Dd + col) = o1;
        }
    }
}

// ---------------------------------------------------------------------------
// FUSED attention: blocks [0,2048) = static chunks (32 per bh),
// blocks [2048, 2048+8192) = temporal (4 s per block).
// ---------------------------------------------------------------------------
#define QP 68
#define NSTATIC (64*NCHUNK)        // 2048
#define SEP 132                    // se row stride (16B-aligned)
#define FUSED_SMEM_FLOATS 6224
#define FUSED_SMEM_B (FUSED_SMEM_FLOATS*4)

__global__ __launch_bounds__(256, 4) void attn_fused(
    const float* __restrict__ Qt, const float* __restrict__ Kt,
    const float* __restrict__ Vt, const float* __restrict__ Qs,
    const float* __restrict__ Ksp, const float* __restrict__ Vsp,
    const int* __restrict__ mt, const int* __restrict__ ms,
    float* __restrict__ w_t, float* __restrict__ qkvt,
    float* __restrict__ w_s, float* __restrict__ smax,
    float* __restrict__ ssum, float* __restrict__ pout)
{
    extern __shared__ __align__(16) float sb[];
    const int tid = threadIdx.x;

    if (blockIdx.x < NSTATIC) {
        // ================= static branch: one (bh, chunk) =================
        const int chunk = blockIdx.x & (NCHUNK-1);
        const int bh = blockIdx.x >> 5;
        const int b = bh >> 3, h = bh & 7;

        float* sq = sb;                  // [16][68]   1088
        float* sk = sb + 1088;           // [32][68]   2176
        float* se = sb + 3264;           // [16][132]  2112
        float* rowmax = sb + 5376;       // [16]

        const int key0 = chunk * CH;
        const int kcnt = min(CH, NKEY - key0);   // 129 or 113

        {
            int qq = tid >> 4, c4 = tid & 15;
            float4 v = *(const float4*)(Qs + (size_t)(b*SSq + qq)*Dd + h*DH + c4*4);
            *(float4*)&sq[qq*68 + c4*4] = v;
        }
        __syncthreads();

        for (int t = 0; t*32 < kcnt; t++) {
            int cnt = min(32, kcnt - t*32);
            for (int i = tid; i < cnt*16; i += 256) {
                int kk = i >> 4, c4 = i & 15;
                int n = key0 + t*32 + kk;
                const float* kp = (n < SMf)
                    ? Kt + (size_t)(b*SMf + n)*Dd + h*DH
                    : Ksp + (size_t)(b*KSn + n - SMf)*Dd + h*DH;
                *(float4*)&sk[kk*68 + c4*4] = *(const float4*)(kp + c4*4);
            }
            __syncthreads();
            for (int p = tid; p < cnt*16; p += 256) {
                int qq = p & 15, kk = p >> 4;
                const float4* qp = (const float4*)&sq[qq*68];
                const float4* kp = (const float4*)&sk[kk*68];
                float acc = 0.f;
#pragma unroll
                for (int c = 0; c < 16; c++) {
                    float4 av = qp[c], bv = kp[c];
                    acc += av.x*bv.x + av.y*bv.y + av.z*bv.z + av.w*bv.w;
                }
                int n = key0 + t*32 + kk;
                int mv = (n < SMf) ? mt[b*SMf + n] : ms[b*KSn + n - SMf];
                se[qq*SEP + t*32 + kk] = acc * SCALE + (mv ? 0.f : -1e30f);
            }
            __syncthreads();
        }

        const int q = tid >> 4, l = tid & 15;
        float lm = -1e38f;
        for (int j = l; j < kcnt; j += 16) lm = fmaxf(lm, se[q*SEP + j]);
#pragma unroll
        for (int o = 8; o > 0; o >>= 1)
            lm = fmaxf(lm, __shfl_xor_sync(0xffffffffu, lm, o));
        if (l == 0) rowmax[q] = lm;
        __syncthreads();
        const float rm = rowmax[q];
        float ls = 0.f;
        const size_t wbase = ((size_t)bh*SSq + q) * (size_t)NKEY + key0;
        for (int j = l; j < kcnt; j += 16) {
            float e = __expf(se[q*SEP + j] - rm);
            se[q*SEP + j] = e;
            w_s[wbase + j] = e;
            ls += e;
        }
#pragma unroll
        for (int o = 8; o > 0; o >>= 1)
            ls += __shfl_xor_sync(0xffffffffu, ls, o);
        if (l == 0) {
            int si = (bh*NCHUNK + chunk)*16 + q;
            smax[si] = rm; ssum[si] = ls;
        }
        __syncthreads();

        const int grp = tid >> 6, d = tid & 63;
        float acc[16];
#pragma unroll
        for (int i = 0; i < 16; i++) acc[i] = 0.f;
        for (int j = grp; j < kcnt; j += 4) {
            int n = key0 + j;
            const float* vp = (n < SMf)
                ? Vt + (size_t)(b*SMf + n)*Dd + h*DH
                : Vsp + (size_t)(b*KSn + n - SMf)*Dd + h*DH;
            float vv = vp[d];
#pragma unroll
            for (int qq = 0; qq < 16; qq++) acc[qq] += se[qq*SEP + j] * vv;
        }
        const size_t pb = ((size_t)((bh*NCHUNK + chunk)*4 + grp) * 16) * 64 + d;
#pragma unroll
        for (int qq = 0; qq < 16; qq++)
            pout[pb + (size_t)qq*64] = acc[qq];

    } else {
        // ================= temporal branch =================
        const int bx = blockIdx.x - NSTATIC;
        const int g  = tid >> 6;
        const int d  = tid & 63;
        const int s4 = bx % (Ss_/4);
        const int h  = (bx / (Ss_/4)) % Hh;
        const int b  = bx / ((Ss_/4) * Hh);
        const int s  = s4 * 4 + g;

        float* q  = sb;                  // [4][8][68]
        float* k  = sb + 2176;
        float* ks = sb + 4352;           // [16][68]
        float* sc = sb + 5440;           // [4][8][24]

        const size_t base_t = ((size_t)(b*Ss_ + s) * Mm) * Dd + (size_t)h * DH;
#pragma unroll
        for (int m = 0; m < Mm; m++) {
            q[(g*Mm + m)*QP + d] = Qt[base_t + (size_t)m*Dd + d];
            k[(g*Mm + m)*QP + d] = Kt[base_t + (size_t)m*Dd + d];
        }
        const size_t base_s = (size_t)b*KSn*Dd + (size_t)h*DH;
#pragma unroll
        for (int i = 0; i < 4; i++) {
            int n = g * 4 + i;
            ks[n*QP + d] = Ksp[base_s + (size_t)n*Dd + d];
        }
        __syncthreads();

        for (int e = d; e < Mm*(Mm+KSn); e += 64) {
            int m = e / (Mm+KSn), n = e % (Mm+KSn);
            const float4* kp = (const float4*)((n < Mm) ? &k[(g*Mm + n)*QP]
                                                        : &ks[(n-Mm)*QP]);
            const float4* qp = (const float4*)&q[(g*Mm + m)*QP];
            float acc = 0.f;
#pragma unroll
            for (int c = 0; c < DH/4; c++) {
                float4 av = qp[c], bv = kp[c];
                acc += av.x*bv.x + av.y*bv.y + av.z*bv.z + av.w*bv.w;
            }
            int maskv = (n < Mm) ? mt[(b*Ss_+s)*Mm + n] : ms[b*KSn + (n-Mm)];
            sc[(g*Mm + m)*24 + n] = acc * SCALE + (maskv ? 0.f : -1e30f);
        }
        __syncthreads();

        {
            const int m = d >> 3;
            const int l = d & 7;
            float* scr = &sc[(g*Mm + m)*24];
            float s0 = scr[l], s1 = scr[l+8], s2 = scr[l+16];
            float lm = fmaxf(s0, fmaxf(s1, s2));
#pragma unroll
            for (int o = 4; o > 0; o >>= 1)
                lm = fmaxf(lm, __shfl_xor_sync(0xffffffffu, lm, o, 8));
            float e0 = __expf(s0 - lm), e1 = __expf(s1 - lm), e2 = __expf(s2 - lm);
            float ls = e0 + e1 + e2;
#pragma unroll
            for (int o = 4; o > 0; o >>= 1)
                ls += __shfl_xor_sync(0xffffffffu, ls, o, 8);
            const float inv = 1.f / ls;
            e0 *= inv; e1 *= inv; e2 *= inv;
            scr[l] = e0; scr[l+8] = e1; scr[l+16] = e2;
            const size_t wb = ((((size_t)(b*Hh+h)*Ss_ + s) * Mm) + m) * (Mm+KSn);
            w_t[wb + l]      = e0;
            w_t[wb + l + 8]  = e1;
            w_t[wb + l + 16] = e2;
        }
        __syncthreads();

        {
            float accv[Mm];
#pragma unroll
            for (int m = 0; m < Mm; m++) accv[m] = 0.f;
#pragma unroll
            for (int n = 0; n < Mm; n++) {
                float vv = Vt[base_t + (size_t)n*Dd + d];
#pragma unroll
                for (int m = 0; m < Mm; m++)
                    accv[m] += sc[(g*Mm + m)*24 + n] * vv;
            }
#pragma unroll
            for (int n = 0; n < KSn; n++) {
                float vv = Vsp[base_s + (size_t)n*Dd + d];
#pragma unroll
                for (int m = 0; m < Mm; m++)
                    accv[m] += sc[(g*Mm + m)*24 + Mm + n] * vv;
            }
#pragma unroll
            for (int m = 0; m < Mm; m++)
                qkvt[base_t + (size_t)m*Dd + d] = accv[m];
        }
    }
}

// ---------------------------------------------------------------------------
// Static attention pass 2: combine 32 chunk partials
// ---------------------------------------------------------------------------
__global__ __launch_bounds__(128) void static_pass2(
    const float* __restrict__ smax, const float* __restrict__ ssum,
    const float* __restrict__ pout, float* __restrict__ w_s,
    float* __restrict__ qkvs)
{
    const int q = blockIdx.x & 15;
    const int bh = blockIdx.x >> 4;
    const int b = bh >> 3, h = bh & 7;
    const int tid = threadIdx.x;

    __shared__ float fac[NCHUNK];

    float gmax = -1e38f;
#pragma unroll
    for (int c = 0; c < NCHUNK; c++)
        gmax = fmaxf(gmax, smax[(bh*NCHUNK + c)*16 + q]);
    float Z = 0.f;
#pragma unroll
    for (int c = 0; c < NCHUNK; c++)
        Z += ssum[(bh*NCHUNK + c)*16 + q]
           * __expf(smax[(bh*NCHUNK + c)*16 + q] - gmax);
    const float invZ = 1.f / Z;
    if (tid < NCHUNK)
        fac[tid] = __expf(smax[(bh*NCHUNK + tid)*16 + q] - gmax) * invZ;
    __syncthreads();

    if (tid < 64) {
        float o = 0.f;
#pragma unroll
        for (int c = 0; c < NCHUNK; c++) {
            float s4 = 0.f;
            size_t pb = ((size_t)((bh*NCHUNK + c)*4) * 16 + q) * 64 + tid;
#pragma unroll
            for (int g = 0; g < 4; g++) s4 += pout[pb + (size_t)g*16*64];
            o += fac[c] * s4;
        }
        qkvs[(size_t)(b*SSq + q)*Dd + h*DH + tid] = o;
    }

    const size_t wbase = ((size_t)bh*SSq + q) * (size_t)NKEY;
    for (int n = tid; n < NKEY; n += 128)
        w_s[wbase + n] *= fac[n / CH];
}

// ---------------------------------------------------------------------------
extern "C" void kernel_launch(void* const* d_in, const int* in_sizes, int n_in,
                              void* d_out, int out_size)
{
    (void)in_sizes; (void)n_in; (void)out_size;
    const float* q_t = (const float*)d_in[0];
    const float* k_t = (const float*)d_in[1];
    const float* v_t = (const float*)d_in[2];
    const float* q_s = (const float*)d_in[3];
    const float* k_s = (const float*)d_in[4];
    const float* v_s = (const float*)d_in[5];
    const int*   m_t = (const int*)d_in[6];
    const int*   m_s = (const int*)d_in[7];
    const float* Wq = (const float*)d_in[8];
    const float* bq = (const float*)d_in[9];
    const float* Wk = (const float*)d_in[10];
    const float* bk = (const float*)d_in[11];
    const float* Wv = (const float*)d_in[12];
    const float* bv = (const float*)d_in[13];
    const float* Wo = (const float*)d_in[14];
    const float* bo = (const float*)d_in[15];

    float* out   = (float*)d_out;
    float* out_t = out;
    float* w_t   = out_t + (size_t)Bb*Ss_*Mm*Dd;
    float* out_s = w_t + (size_t)Bb*Hh*Ss_*Mm*(Mm+KSn);
    float* w_s   = out_s + (size_t)Bb*SSq*Dd;

    float *p_qt, *p_kt, *p_vt, *p_qkvt, *p_qs, *p_ks, *p_vs, *p_qkvs;
    float *p_smax, *p_ssum, *p_pout;
    __half *p_wt;
    cudaGetSymbolAddress((void**)&p_qt,   g_qt);
    cudaGetSymbolAddress((void**)&p_kt,   g_kt);
    cudaGetSymbolAddress((void**)&p_vt,   g_vt);
    cudaGetSymbolAddress((void**)&p_qkvt, g_qkvt);
    cudaGetSymbolAddress((void**)&p_qs,   g_qs);
    cudaGetSymbolAddress((void**)&p_ks,   g_ks);
    cudaGetSymbolAddress((void**)&p_vs,   g_vs);
    cudaGetSymbolAddress((void**)&p_qkvs, g_qkvs);
    cudaGetSymbolAddress((void**)&p_wt,   g_wt);
    cudaGetSymbolAddress((void**)&p_smax, g_smax);
    cudaGetSymbolAddress((void**)&p_ssum, g_ssum);
    cudaGetSymbolAddress((void**)&p_pout, g_pout);

    const size_t WSZ = (size_t)Dd * Dd;
    __half* wq = p_wt + 0*WSZ;
    __half* wk = p_wt + 1*WSZ;
    __half* wv = p_wt + 2*WSZ;
    __half* wo = p_wt + 3*WSZ;

    cudaFuncSetAttribute(mma_gemm, cudaFuncAttributeMaxDynamicSharedMemorySize,
                         DSMEM2_B);

    // 1) weight transpose + fp16 convert
    WArgs wa;
    wa.W[0] = Wq; wa.Wt[0] = wq;
    wa.W[1] = Wk; wa.Wt[1] = wk;
    wa.W[2] = Wv; wa.Wt[2] = wv;
    wa.W[3] = Wo; wa.Wt[3] = wo;
    wsplit_kernel<<<dim3(16,16,4), dim3(32,8)>>>(wa);

    // 2) all six input projections
    GBatch pb;
    pb.g[0] = { q_t, wq, bq, p_qt, TROWS };
    pb.g[1] = { k_t, wk, bk, p_kt, TROWS };
    pb.g[2] = { v_t, wv, bv, p_vt, TROWS };
    pb.g[3] = { q_s, wq, bq, p_qs, SROWS };
    pb.g[4] = { k_s, wk, bk, p_ks, SROWS };
    pb.g[5] = { v_s, wv, bv, p_vs, SROWS };
    mma_gemm<<<dim3(4, 256, 6), 256, DSMEM2_B>>>(pb);

    // 3) fused attention + combine
    attn_fused<<<NSTATIC + Bb*Hh*(Ss_/4), 256, FUSED_SMEM_B>>>(
        p_qt, p_kt, p_vt, p_qs, p_ks, p_vs, m_t, m_s,
        w_t, p_qkvt, w_s, p_smax, p_ssum, p_pout);
    static_pass2<<<1024, 128>>>(p_smax, p_ssum, p_pout, w_s, p_qkvs);

    // 4) output projections (2 real GEMMs)
    GBatch ob;
    ob.g[0] = { p_qkvt, wo, bo, out_t, TROWS };
    ob.g[1] = { p_qkvs, wo, bo, out_s, SROWS };
    ob.g[2] = ob.g[1]; ob.g[3] = ob.g[1]; ob.g[4] = ob.g[1]; ob.g[5] = ob.g[1];
    mma_gemm<<<dim3(4, 256, 2), 256, DSMEM2_B>>>(ob);
}